// round 9
// baseline (speedup 1.0000x reference)
#include <cuda_runtime.h>
#include <cuda_bf16.h>
#include <cstdint>

#define N_NODES  50000
#define N_REL    16
#define HID      128
#define N_LAYERS 3
#define N_EDGES  1600000
#define NSEG     (N_NODES * N_REL)   // 800000
#define NCHUNK   (N_REL + 1)         // 16 relations + root
#define W_ELEMS  (N_LAYERS * NCHUNK * 16384)
#define STRIPE   12800               // nodes per L2 stripe (4 stripes)

// ================= device scratch (no cudaMalloc allowed) =================
__device__ __align__(16) __nv_bfloat16 g_agghi[(size_t)N_NODES * N_REL * HID];
__device__ __align__(16) __nv_bfloat16 g_agglo[(size_t)N_NODES * N_REL * HID];
__device__ __align__(16) float g_bufA[(size_t)N_NODES * HID];
__device__ __align__(16) float g_bufB[(size_t)N_NODES * HID];
// weight stack: per layer 17 tiles of [n][k] bf16 (16 relations + root)
__device__ __align__(16) __nv_bfloat16 g_whi[(size_t)W_ELEMS];
__device__ __align__(16) __nv_bfloat16 g_wlo[(size_t)W_ELEMS];
__device__ int g_cnt[NSEG];
__device__ int g_segstart[NSEG];  // block-local scan (finalize with blkoff)
__device__ int g_cursor[NSEG];
__device__ int g_blksum[1024];
__device__ int g_blkoff[1024];
__device__ int g_eseg[N_EDGES];
__device__ int g_esrc[N_EDGES];
__device__ int g_srcSorted[N_EDGES];

// ================= helpers =================
__device__ __forceinline__ uint32_t smem_to_u32(const void* p) {
    uint32_t a;
    asm("{ .reg .u64 t; cvta.to.shared.u64 t, %1; cvt.u32.u64 %0, t; }"
        : "=r"(a) : "l"(p));
    return a;
}
__device__ __forceinline__ void ldsm_x4(uint32_t* r, uint32_t addr) {
    asm volatile("ldmatrix.sync.aligned.m8n8.x4.shared.b16 {%0,%1,%2,%3}, [%4];"
        : "=r"(r[0]), "=r"(r[1]), "=r"(r[2]), "=r"(r[3]) : "r"(addr));
}
__device__ __forceinline__ void mma_bf16(float* d, const uint32_t* a, const uint32_t* b) {
    asm volatile("mma.sync.aligned.m16n8k16.row.col.f32.bf16.bf16.f32 "
        "{%0,%1,%2,%3}, {%4,%5,%6,%7}, {%8,%9}, {%0,%1,%2,%3};"
        : "+f"(d[0]), "+f"(d[1]), "+f"(d[2]), "+f"(d[3])
        : "r"(a[0]), "r"(a[1]), "r"(a[2]), "r"(a[3]), "r"(b[0]), "r"(b[1]));
}
__device__ __forceinline__ void split_store(char* hi, char* lo, float a, float b) {
    __nv_bfloat16 h0 = __float2bfloat16(a), h1 = __float2bfloat16(b);
    __nv_bfloat16 l0 = __float2bfloat16(a - __bfloat162float(h0));
    __nv_bfloat16 l1 = __float2bfloat16(b - __bfloat162float(h1));
    *(__nv_bfloat162*)hi = __nv_bfloat162(h0, h1);
    *(__nv_bfloat162*)lo = __nv_bfloat162(l0, l1);
}

// ================= prep (5 launches) =======================================
__global__ void prep0_kernel(const float* __restrict__ W,
                             const float* __restrict__ root) {
    int t = blockIdx.x * blockDim.x + threadIdx.x;
    if (t < NSEG) { g_cnt[t] = 0; g_cursor[t] = 0; }
    if (t < W_ELEMS) {
        int tt  = t >> 14;
        int rem = t & 16383;
        int n = rem >> 7;
        int k = rem & 127;
        int l = tt / NCHUNK;
        int c = tt % NCHUNK;
        float v;
        if (c < N_REL) v = W[(((size_t)l * N_REL + c) * HID + k) * HID + n];
        else           v = root[((size_t)l * HID + k) * HID + n];
        __nv_bfloat16 hi = __float2bfloat16(v);
        __nv_bfloat16 lo = __float2bfloat16(v - __bfloat162float(hi));
        size_t off = (size_t)tt * 16384 + n * HID + k;
        g_whi[off] = hi;
        g_wlo[off] = lo;
    }
}
__global__ void prep_edges_kernel(const int* __restrict__ edge_index,
                                  const int* __restrict__ edge_type) {
    int e = blockIdx.x * blockDim.x + threadIdx.x;
    if (e >= N_EDGES) return;
    int s = edge_index[e];
    int t = edge_index[N_EDGES + e];
    int r = edge_type[e];
    if ((unsigned)s >= N_NODES || (unsigned)t >= N_NODES || (unsigned)r >= N_REL) {
        g_eseg[e] = -1; g_esrc[e] = 0; return;
    }
    g_eseg[e] = t * N_REL + r;
    g_esrc[e] = s;
    atomicAdd(&g_cnt[t * N_REL + r], 1);
}
__global__ void scan1_kernel() {
    __shared__ int s[256];
    int base = blockIdx.x * 1024;
    int t = threadIdx.x;
    int v[4]; int sum = 0;
    #pragma unroll
    for (int j = 0; j < 4; j++) {
        int idx = base + t * 4 + j;
        v[j] = (idx < NSEG) ? g_cnt[idx] : 0;
        sum += v[j];
    }
    s[t] = sum; __syncthreads();
    for (int off = 1; off < 256; off <<= 1) {
        int x = 0;
        if (t >= off) x = s[t - off];
        __syncthreads();
        if (t >= off) s[t] += x;
        __syncthreads();
    }
    int excl = (t > 0) ? s[t - 1] : 0;
    if (t == 255) g_blksum[blockIdx.x] = s[255];
    int run = excl;
    #pragma unroll
    for (int j = 0; j < 4; j++) {
        int idx = base + t * 4 + j;
        if (idx < NSEG) g_segstart[idx] = run;
        run += v[j];
    }
}
__global__ void scan2_kernel(int nb) {
    __shared__ int s[256];
    int t = threadIdx.x;
    int v[4]; int sum = 0;
    #pragma unroll
    for (int j = 0; j < 4; j++) {
        int idx = t * 4 + j;
        v[j] = (idx < nb) ? g_blksum[idx] : 0;
        sum += v[j];
    }
    s[t] = sum; __syncthreads();
    for (int off = 1; off < 256; off <<= 1) {
        int x = 0;
        if (t >= off) x = s[t - off];
        __syncthreads();
        if (t >= off) s[t] += x;
        __syncthreads();
    }
    int excl = (t > 0) ? s[t - 1] : 0;
    int run = excl;
    #pragma unroll
    for (int j = 0; j < 4; j++) {
        int idx = t * 4 + j;
        if (idx < nb) g_blkoff[idx] = run;
        run += v[j];
    }
}
__global__ void bin_edges_kernel() {
    int e = blockIdx.x * blockDim.x + threadIdx.x;
    if (e >= N_EDGES) return;
    int seg = g_eseg[e];
    if (seg < 0) return;
    int base = g_segstart[seg] + g_blkoff[seg >> 10];
    int pos = base + atomicAdd(&g_cursor[seg], 1);
    g_srcSorted[pos] = g_esrc[e];
}

// ================= per-stripe aggregation (no atomics) =====================
// One warp per (node,rel) segment within the stripe. x is pre-activated.
// Writes split-bf16 agg rows; stores use default caching (L2-resident for
// the immediately following GEMM stripe).
__global__ __launch_bounds__(256) void agg_kernel(const float* __restrict__ x,
                                                  int segBase, int nSegs)
{
    int w = (blockIdx.x * 256 + threadIdx.x) >> 5;
    int lane = threadIdx.x & 31;
    if (w >= nSegs) return;
    int seg = segBase + w;
    int st = g_segstart[seg] + g_blkoff[seg >> 10];
    int c  = g_cnt[seg];
    float4 sum = make_float4(0.f, 0.f, 0.f, 0.f);
    for (int i = 0; i < c; i++) {
        int s = __ldg(g_srcSorted + st + i);
        float4 v = __ldg((const float4*)(x + (size_t)s * HID) + lane);
        sum.x += v.x; sum.y += v.y; sum.z += v.z; sum.w += v.w;
    }
    float inv = (c > 0) ? 1.0f / (float)c : 0.0f;
    sum.x *= inv; sum.y *= inv; sum.z *= inv; sum.w *= inv;

    __nv_bfloat16 h0 = __float2bfloat16(sum.x), h1 = __float2bfloat16(sum.y);
    __nv_bfloat16 h2 = __float2bfloat16(sum.z), h3 = __float2bfloat16(sum.w);
    __nv_bfloat16 l0 = __float2bfloat16(sum.x - __bfloat162float(h0));
    __nv_bfloat16 l1 = __float2bfloat16(sum.y - __bfloat162float(h1));
    __nv_bfloat16 l2 = __float2bfloat16(sum.z - __bfloat162float(h2));
    __nv_bfloat16 l3 = __float2bfloat16(sum.w - __bfloat162float(h3));
    // seg*128 == node*2048 + rel*128 (seg = node*16 + rel)
    size_t off = (size_t)seg * HID + lane * 4;
    __nv_bfloat162 H0(h0, h1), H1(h2, h3), L0(l0, l1), L1(l2, l3);
    uint2 Hp, Lp;
    Hp.x = *(uint32_t*)&H0; Hp.y = *(uint32_t*)&H1;
    Lp.x = *(uint32_t*)&L0; Lp.y = *(uint32_t*)&L1;
    *(uint2*)(g_agghi + off) = Hp;
    *(uint2*)(g_agglo + off) = Lp;
}

// ================= stripe GEMM: out = [agg | x] @ [Wstk; root] + bias ======
// K = 17 chunks x 128. 512 threads / 16 warps (32x32 warp tiles).
#define TPAD      136
#define TILE_B    (128 * TPAD * 2)           // 34816 bytes
#define SM_AHI    0
#define SM_ALO    (SM_AHI + TILE_B)
#define SM_BHI    (SM_ALO + TILE_B)
#define SM_BLO    (SM_BHI + TILE_B)
#define SM_TOTAL  (SM_BLO + TILE_B)          // 139264

__global__ __launch_bounds__(512) void rgcn_gemm(
    const float* __restrict__ xin,
    const __nv_bfloat16* __restrict__ whi,   // layer's 17-tile stack
    const __nv_bfloat16* __restrict__ wlo,
    const float* __restrict__ bias,
    float* __restrict__ out,
    int stripeBase, int stripeEnd, int reluStore)
{
    extern __shared__ __align__(16) char smem[];
    const uint32_t sb = smem_to_u32(smem);
    const int tid  = threadIdx.x;
    const int wid  = tid >> 5;
    const int lane = tid & 31;
    const int rowBase = stripeBase + blockIdx.x * 128;

    const int mW = (wid & 3) * 32;
    const int nW = (wid >> 2) * 32;

    float acc[2][4][4];
    #pragma unroll
    for (int mt = 0; mt < 2; mt++)
        #pragma unroll
        for (int nt = 0; nt < 4; nt++)
            #pragma unroll
            for (int q = 0; q < 4; q++) acc[mt][nt][q] = 0.0f;

    for (int kc = 0; kc < NCHUNK; kc++) {
        __syncthreads();   // prior chunk's ldsm reads complete
        // ---- A chunk ----
        if (kc < N_REL) {
            // split-bf16 agg chunk: 128 rows x 256B per array (4 fl4/thread each)
            #pragma unroll
            for (int i = 0; i < 4; i++) {
                int idx4 = tid + i * 512;        // 0..2047
                int row = idx4 >> 4, c16 = idx4 & 15;
                int gr = rowBase + row;
                float4 vh = make_float4(0.f,0.f,0.f,0.f), vl = vh;
                if (gr < stripeEnd) {
                    size_t o = (size_t)gr * (N_REL * HID) + kc * HID + c16 * 8;
                    vh = *(const float4*)(g_agghi + o);
                    vl = *(const float4*)(g_agglo + o);
                }
                *(float4*)(smem + SM_AHI + row * (TPAD*2) + c16 * 16) = vh;
                *(float4*)(smem + SM_ALO + row * (TPAD*2) + c16 * 16) = vl;
            }
        } else {
            // root chunk: fp32 x (pre-activated) + split (8 fl4/thread)
            #pragma unroll
            for (int i = 0; i < 8; i++) {
                int idx4 = tid + i * 512;        // 0..4095
                int row = idx4 >> 5, kq = (idx4 & 31) << 2;
                int gr = rowBase + row;
                float4 v = make_float4(0.f,0.f,0.f,0.f);
                if (gr < stripeEnd) v = *(const float4*)(xin + (size_t)gr * HID + kq);
                uint32_t boff = (uint32_t)row * (TPAD * 2) + kq * 2;
                split_store(smem + SM_AHI + boff,     smem + SM_ALO + boff,     v.x, v.y);
                split_store(smem + SM_AHI + boff + 4, smem + SM_ALO + boff + 4, v.z, v.w);
            }
        }
        // ---- B chunk (L2-resident weight stack), 4 fl4/thread ----
        {
            const __nv_bfloat16* bh = whi + (size_t)kc * 16384;
            const __nv_bfloat16* bl = wlo + (size_t)kc * 16384;
            #pragma unroll
            for (int i = 0; i < 4; i++) {
                int idx4 = tid + i * 512;        // 0..2047
                int row = idx4 >> 4, c16 = idx4 & 15;
                *(float4*)(smem + SM_BHI + row * (TPAD*2) + c16 * 16) =
                    *(const float4*)(bh + row * HID + c16 * 8);
                *(float4*)(smem + SM_BLO + row * (TPAD*2) + c16 * 16) =
                    *(const float4*)(bl + row * HID + c16 * 8);
            }
        }
        __syncthreads();

        // ---- MMA: 3 split terms over this 128-K chunk ----
        #pragma unroll
        for (int term = 0; term < 3; term++) {
            const uint32_t aBase = sb + (term == 2 ? SM_ALO : SM_AHI);
            const uint32_t bBase = sb + (term == 1 ? SM_BLO : SM_BHI);
            #pragma unroll
            for (int k0 = 0; k0 < HID; k0 += 16) {
                uint32_t a[2][4];
                {
                    int ar = mW + (lane & 15);
                    int ac = k0 + ((lane >> 4) << 3);
                    ldsm_x4(a[0], aBase + (uint32_t)ar * (TPAD*2) + ac * 2);
                    ldsm_x4(a[1], aBase + (uint32_t)(ar + 16) * (TPAD*2) + ac * 2);
                }
                uint32_t b[4][2];
                #pragma unroll
                for (int p = 0; p < 2; p++) {
                    int g  = lane >> 3;
                    int nn = nW + p * 16 + (lane & 7) + ((g >> 1) << 3);
                    int kk = k0 + ((g & 1) << 3);
                    uint32_t r[4];
                    ldsm_x4(r, bBase + (uint32_t)nn * (TPAD*2) + kk * 2);
                    b[p*2][0] = r[0]; b[p*2][1] = r[1];
                    b[p*2+1][0] = r[2]; b[p*2+1][1] = r[3];
                }
                #pragma unroll
                for (int mt = 0; mt < 2; mt++)
                    #pragma unroll
                    for (int nt = 0; nt < 4; nt++)
                        mma_bf16(acc[mt][nt], a[mt], b[nt]);
            }
        }
    }

    // ---- epilogue: + bias (+ relu for intermediate layers), store ----
    #pragma unroll
    for (int mt = 0; mt < 2; mt++) {
        int r0 = rowBase + mW + mt * 16 + (lane >> 2);
        int r1 = r0 + 8;
        #pragma unroll
        for (int nt = 0; nt < 4; nt++) {
            int col = nW + nt * 8 + (lane & 3) * 2;
            float b0 = bias[col], b1 = bias[col + 1];
            float v00 = acc[mt][nt][0] + b0, v01 = acc[mt][nt][1] + b1;
            float v10 = acc[mt][nt][2] + b0, v11 = acc[mt][nt][3] + b1;
            if (reluStore) {
                v00 = fmaxf(v00, 0.f); v01 = fmaxf(v01, 0.f);
                v10 = fmaxf(v10, 0.f); v11 = fmaxf(v11, 0.f);
            }
            if (r0 < stripeEnd)
                *(float2*)(out + (size_t)r0 * HID + col) = make_float2(v00, v01);
            if (r1 < stripeEnd)
                *(float2*)(out + (size_t)r1 * HID + col) = make_float2(v10, v11);
        }
    }
}

// ================= launch ================================================
extern "C" void kernel_launch(void* const* d_in, const int* in_sizes, int n_in,
                              void* d_out, int out_size)
{
    const int*   edge_index = (const int*)d_in[0];
    const int*   edge_type  = (const int*)d_in[1];
    const float* node_init  = (const float*)d_in[2];
    const float* W          = (const float*)d_in[3];
    const float* root       = (const float*)d_in[4];
    const float* bias       = (const float*)d_in[5];
    float*       out        = (float*)d_out;

    void* p;
    cudaGetSymbolAddress(&p, g_bufA); float* bufA = (float*)p;
    cudaGetSymbolAddress(&p, g_bufB); float* bufB = (float*)p;
    cudaGetSymbolAddress(&p, g_whi);  __nv_bfloat16* whi = (__nv_bfloat16*)p;
    cudaGetSymbolAddress(&p, g_wlo);  __nv_bfloat16* wlo = (__nv_bfloat16*)p;

    cudaFuncSetAttribute(rgcn_gemm,
                         cudaFuncAttributeMaxDynamicSharedMemorySize, SM_TOTAL);

    const int scanBlocks = (NSEG + 1023) / 1024;   // 782
    prep0_kernel<<<(W_ELEMS + 255) / 256, 256>>>(W, root);
    prep_edges_kernel<<<(N_EDGES + 255) / 256, 256>>>(edge_index, edge_type);
    scan1_kernel<<<scanBlocks, 256>>>();
    scan2_kernel<<<1, 256>>>(scanBlocks);
    bin_edges_kernel<<<(N_EDGES + 255) / 256, 256>>>();

    const float* xin = node_init;
    for (int l = 0; l < N_LAYERS; l++) {
        float* xout = (l == N_LAYERS - 1) ? out : (l == 0 ? bufA : bufB);
        int reluStore = (l < N_LAYERS - 1) ? 1 : 0;
        for (int s0 = 0; s0 < N_NODES; s0 += STRIPE) {
            int s1 = (s0 + STRIPE < N_NODES) ? s0 + STRIPE : N_NODES;
            int nNodes = s1 - s0;
            int nSegs  = nNodes * N_REL;
            agg_kernel<<<(nSegs + 7) / 8, 256>>>(xin, s0 * N_REL, nSegs);
            rgcn_gemm<<<(nNodes + 127) / 128, 512, SM_TOTAL>>>(
                xin, whi + (size_t)l * NCHUNK * 16384,
                wlo + (size_t)l * NCHUNK * 16384,
                bias + (size_t)l * HID, xout, s0, s1, reluStore);
        }
        xin = xout;
    }
}

// round 10
// speedup vs baseline: 1.2917x; 1.2917x over previous
#include <cuda_runtime.h>
#include <cuda_bf16.h>
#include <cstdint>

#define N_NODES  50000
#define N_REL    16
#define HID      128
#define N_LAYERS 3
#define N_EDGES  1600000
#define NSEG     (N_NODES * N_REL)   // 800000
#define KTOT     (N_REL * HID)       // 2048
#define NCHUNK   (N_REL + 1)         // 16 relations + root
#define W_ELEMS  (N_LAYERS * NCHUNK * 16384)

// ================= device scratch (no cudaMalloc allowed) =================
__device__ __align__(16) __nv_bfloat16 g_agghi[(size_t)N_NODES * KTOT]; // 204.8 MB
__device__ __align__(16) __nv_bfloat16 g_agglo[(size_t)N_NODES * KTOT]; // 204.8 MB
__device__ __align__(16) float g_bufA[(size_t)N_NODES * HID];
__device__ __align__(16) float g_bufB[(size_t)N_NODES * HID];
// weight stack: per layer 17 tiles of [n][k] bf16 (16 relations + root)
__device__ __align__(16) __nv_bfloat16 g_whi[(size_t)W_ELEMS];
__device__ __align__(16) __nv_bfloat16 g_wlo[(size_t)W_ELEMS];
__device__ int g_cnt[NSEG];
__device__ int g_segstart[NSEG];  // block-local scan (finalize with blkoff)
__device__ int g_cursor[NSEG];
__device__ int g_blksum[1024];
__device__ int g_blkoff[1024];
__device__ int g_eseg[N_EDGES];
__device__ int g_esrc[N_EDGES];
__device__ int g_srcSorted[N_EDGES];

// ================= helpers =================
__device__ __forceinline__ uint32_t smem_to_u32(const void* p) {
    uint32_t a;
    asm("{ .reg .u64 t; cvta.to.shared.u64 t, %1; cvt.u32.u64 %0, t; }"
        : "=r"(a) : "l"(p));
    return a;
}
__device__ __forceinline__ void ldsm_x4(uint32_t* r, uint32_t addr) {
    asm volatile("ldmatrix.sync.aligned.m8n8.x4.shared.b16 {%0,%1,%2,%3}, [%4];"
        : "=r"(r[0]), "=r"(r[1]), "=r"(r[2]), "=r"(r[3]) : "r"(addr));
}
__device__ __forceinline__ void mma_bf16(float* d, const uint32_t* a, const uint32_t* b) {
    asm volatile("mma.sync.aligned.m16n8k16.row.col.f32.bf16.bf16.f32 "
        "{%0,%1,%2,%3}, {%4,%5,%6,%7}, {%8,%9}, {%0,%1,%2,%3};"
        : "+f"(d[0]), "+f"(d[1]), "+f"(d[2]), "+f"(d[3])
        : "r"(a[0]), "r"(a[1]), "r"(a[2]), "r"(a[3]), "r"(b[0]), "r"(b[1]));
}
__device__ __forceinline__ void split_store(char* hi, char* lo, float a, float b) {
    __nv_bfloat16 h0 = __float2bfloat16(a), h1 = __float2bfloat16(b);
    __nv_bfloat16 l0 = __float2bfloat16(a - __bfloat162float(h0));
    __nv_bfloat16 l1 = __float2bfloat16(b - __bfloat162float(h1));
    *(__nv_bfloat162*)hi = __nv_bfloat162(h0, h1);
    *(__nv_bfloat162*)lo = __nv_bfloat162(l0, l1);
}

// ================= prep (5 launches) =======================================
__global__ void prep0_kernel(const float* __restrict__ W,
                             const float* __restrict__ root) {
    int t = blockIdx.x * blockDim.x + threadIdx.x;
    if (t < NSEG) { g_cnt[t] = 0; g_cursor[t] = 0; }
    if (t < W_ELEMS) {
        int tt  = t >> 14;
        int rem = t & 16383;
        int n = rem >> 7;
        int k = rem & 127;
        int l = tt / NCHUNK;
        int c = tt % NCHUNK;
        float v;
        if (c < N_REL) v = W[(((size_t)l * N_REL + c) * HID + k) * HID + n];
        else           v = root[((size_t)l * HID + k) * HID + n];
        __nv_bfloat16 hi = __float2bfloat16(v);
        __nv_bfloat16 lo = __float2bfloat16(v - __bfloat162float(hi));
        size_t off = (size_t)tt * 16384 + n * HID + k;
        g_whi[off] = hi;
        g_wlo[off] = lo;
    }
}
__global__ void prep_edges_kernel(const int* __restrict__ edge_index,
                                  const int* __restrict__ edge_type) {
    int e = blockIdx.x * blockDim.x + threadIdx.x;
    if (e >= N_EDGES) return;
    int s = edge_index[e];
    int t = edge_index[N_EDGES + e];
    int r = edge_type[e];
    if ((unsigned)s >= N_NODES || (unsigned)t >= N_NODES || (unsigned)r >= N_REL) {
        g_eseg[e] = -1; g_esrc[e] = 0; return;
    }
    g_eseg[e] = t * N_REL + r;
    g_esrc[e] = s;
    atomicAdd(&g_cnt[t * N_REL + r], 1);
}
__global__ void scan1_kernel() {
    __shared__ int s[256];
    int base = blockIdx.x * 1024;
    int t = threadIdx.x;
    int v[4]; int sum = 0;
    #pragma unroll
    for (int j = 0; j < 4; j++) {
        int idx = base + t * 4 + j;
        v[j] = (idx < NSEG) ? g_cnt[idx] : 0;
        sum += v[j];
    }
    s[t] = sum; __syncthreads();
    for (int off = 1; off < 256; off <<= 1) {
        int x = 0;
        if (t >= off) x = s[t - off];
        __syncthreads();
        if (t >= off) s[t] += x;
        __syncthreads();
    }
    int excl = (t > 0) ? s[t - 1] : 0;
    if (t == 255) g_blksum[blockIdx.x] = s[255];
    int run = excl;
    #pragma unroll
    for (int j = 0; j < 4; j++) {
        int idx = base + t * 4 + j;
        if (idx < NSEG) g_segstart[idx] = run;
        run += v[j];
    }
}
__global__ void scan2_kernel(int nb) {
    __shared__ int s[256];
    int t = threadIdx.x;
    int v[4]; int sum = 0;
    #pragma unroll
    for (int j = 0; j < 4; j++) {
        int idx = t * 4 + j;
        v[j] = (idx < nb) ? g_blksum[idx] : 0;
        sum += v[j];
    }
    s[t] = sum; __syncthreads();
    for (int off = 1; off < 256; off <<= 1) {
        int x = 0;
        if (t >= off) x = s[t - off];
        __syncthreads();
        if (t >= off) s[t] += x;
        __syncthreads();
    }
    int excl = (t > 0) ? s[t - 1] : 0;
    int run = excl;
    #pragma unroll
    for (int j = 0; j < 4; j++) {
        int idx = t * 4 + j;
        if (idx < nb) g_blkoff[idx] = run;
        run += v[j];
    }
}
__global__ void bin_edges_kernel() {
    int e = blockIdx.x * blockDim.x + threadIdx.x;
    if (e >= N_EDGES) return;
    int seg = g_eseg[e];
    if (seg < 0) return;
    int base = g_segstart[seg] + g_blkoff[seg >> 10];
    int pos = base + atomicAdd(&g_cursor[seg], 1);
    g_srcSorted[pos] = g_esrc[e];
}

// ================= full-range aggregation (no atomics) =====================
// One warp per (node,rel) segment. x is pre-activated (relu folded into the
// previous layer's epilogue). Streaming stores (.cs): write-once data, keep
// L2 for x.
__global__ __launch_bounds__(256) void agg_kernel(const float* __restrict__ x)
{
    int w = (blockIdx.x * 256 + threadIdx.x) >> 5;
    int lane = threadIdx.x & 31;
    if (w >= NSEG) return;
    int st = g_segstart[w] + g_blkoff[w >> 10];
    int c  = g_cnt[w];
    float4 sum = make_float4(0.f, 0.f, 0.f, 0.f);
    for (int i = 0; i < c; i++) {
        int s = __ldg(g_srcSorted + st + i);
        float4 v = __ldg((const float4*)(x + (size_t)s * HID) + lane);
        sum.x += v.x; sum.y += v.y; sum.z += v.z; sum.w += v.w;
    }
    float inv = (c > 0) ? 1.0f / (float)c : 0.0f;
    sum.x *= inv; sum.y *= inv; sum.z *= inv; sum.w *= inv;

    __nv_bfloat16 h0 = __float2bfloat16(sum.x), h1 = __float2bfloat16(sum.y);
    __nv_bfloat16 h2 = __float2bfloat16(sum.z), h3 = __float2bfloat16(sum.w);
    __nv_bfloat16 l0 = __float2bfloat16(sum.x - __bfloat162float(h0));
    __nv_bfloat16 l1 = __float2bfloat16(sum.y - __bfloat162float(h1));
    __nv_bfloat16 l2 = __float2bfloat16(sum.z - __bfloat162float(h2));
    __nv_bfloat16 l3 = __float2bfloat16(sum.w - __bfloat162float(h3));
    __nv_bfloat162 H0(h0, h1), H1(h2, h3), L0(l0, l1), L1(l2, l3);
    size_t off = (size_t)w * HID + lane * 4;   // seg*128 = node*2048 + rel*128
    asm volatile("st.global.cs.v2.b32 [%0], {%1,%2};"
                 :: "l"(g_agghi + off), "r"(*(uint32_t*)&H0), "r"(*(uint32_t*)&H1) : "memory");
    asm volatile("st.global.cs.v2.b32 [%0], {%1,%2};"
                 :: "l"(g_agglo + off), "r"(*(uint32_t*)&L0), "r"(*(uint32_t*)&L1) : "memory");
}

// ================= layer GEMM: out = [agg | x] @ [Wstk; root] + bias =======
// K = 17 chunks x 128. 512 threads / 16 warps (32x32 warp tiles).
#define TPAD      136
#define TILE_B    (128 * TPAD * 2)           // 34816 bytes
#define SM_AHI    0
#define SM_ALO    (SM_AHI + TILE_B)
#define SM_BHI    (SM_ALO + TILE_B)
#define SM_BLO    (SM_BHI + TILE_B)
#define SM_TOTAL  (SM_BLO + TILE_B)          // 139264

__global__ __launch_bounds__(512) void rgcn_gemm(
    const float* __restrict__ xin,
    const __nv_bfloat16* __restrict__ whi,   // layer's 17-tile stack
    const __nv_bfloat16* __restrict__ wlo,
    const float* __restrict__ bias,
    float* __restrict__ out, int reluStore)
{
    extern __shared__ __align__(16) char smem[];
    const uint32_t sb = smem_to_u32(smem);
    const int tid  = threadIdx.x;
    const int wid  = tid >> 5;
    const int lane = tid & 31;
    const int rowBase = blockIdx.x * 128;

    const int mW = (wid & 3) * 32;
    const int nW = (wid >> 2) * 32;

    float acc[2][4][4];
    #pragma unroll
    for (int mt = 0; mt < 2; mt++)
        #pragma unroll
        for (int nt = 0; nt < 4; nt++)
            #pragma unroll
            for (int q = 0; q < 4; q++) acc[mt][nt][q] = 0.0f;

    for (int kc = 0; kc < NCHUNK; kc++) {
        __syncthreads();   // prior chunk's ldsm reads complete
        // ---- A chunk ----
        if (kc < N_REL) {
            // split-bf16 agg chunk (streamed, read-once): 4 fl4/thread each
            #pragma unroll
            for (int i = 0; i < 4; i++) {
                int idx4 = tid + i * 512;        // 0..2047
                int row = idx4 >> 4, c16 = idx4 & 15;
                int gr = rowBase + row;
                float4 vh = make_float4(0.f,0.f,0.f,0.f), vl = vh;
                if (gr < N_NODES) {
                    size_t o = (size_t)gr * KTOT + kc * HID + c16 * 8;
                    vh = __ldcs((const float4*)(g_agghi + o));
                    vl = __ldcs((const float4*)(g_agglo + o));
                }
                *(float4*)(smem + SM_AHI + row * (TPAD*2) + c16 * 16) = vh;
                *(float4*)(smem + SM_ALO + row * (TPAD*2) + c16 * 16) = vl;
            }
        } else {
            // root chunk: fp32 x (pre-activated) + split (8 fl4/thread)
            #pragma unroll
            for (int i = 0; i < 8; i++) {
                int idx4 = tid + i * 512;        // 0..4095
                int row = idx4 >> 5, kq = (idx4 & 31) << 2;
                int gr = rowBase + row;
                float4 v = make_float4(0.f,0.f,0.f,0.f);
                if (gr < N_NODES) v = *(const float4*)(xin + (size_t)gr * HID + kq);
                uint32_t boff = (uint32_t)row * (TPAD * 2) + kq * 2;
                split_store(smem + SM_AHI + boff,     smem + SM_ALO + boff,     v.x, v.y);
                split_store(smem + SM_AHI + boff + 4, smem + SM_ALO + boff + 4, v.z, v.w);
            }
        }
        // ---- B chunk (L2-resident weight stack), 4 fl4/thread ----
        {
            const __nv_bfloat16* bh = whi + (size_t)kc * 16384;
            const __nv_bfloat16* bl = wlo + (size_t)kc * 16384;
            #pragma unroll
            for (int i = 0; i < 4; i++) {
                int idx4 = tid + i * 512;        // 0..2047
                int row = idx4 >> 4, c16 = idx4 & 15;
                *(float4*)(smem + SM_BHI + row * (TPAD*2) + c16 * 16) =
                    *(const float4*)(bh + row * HID + c16 * 8);
                *(float4*)(smem + SM_BLO + row * (TPAD*2) + c16 * 16) =
                    *(const float4*)(bl + row * HID + c16 * 8);
            }
        }
        __syncthreads();

        // ---- MMA: 3 split terms over this 128-K chunk ----
        #pragma unroll
        for (int term = 0; term < 3; term++) {
            const uint32_t aBase = sb + (term == 2 ? SM_ALO : SM_AHI);
            const uint32_t bBase = sb + (term == 1 ? SM_BLO : SM_BHI);
            #pragma unroll
            for (int k0 = 0; k0 < HID; k0 += 16) {
                uint32_t a[2][4];
                {
                    int ar = mW + (lane & 15);
                    int ac = k0 + ((lane >> 4) << 3);
                    ldsm_x4(a[0], aBase + (uint32_t)ar * (TPAD*2) + ac * 2);
                    ldsm_x4(a[1], aBase + (uint32_t)(ar + 16) * (TPAD*2) + ac * 2);
                }
                uint32_t b[4][2];
                #pragma unroll
                for (int p = 0; p < 2; p++) {
                    int g  = lane >> 3;
                    int nn = nW + p * 16 + (lane & 7) + ((g >> 1) << 3);
                    int kk = k0 + ((g & 1) << 3);
                    uint32_t r[4];
                    ldsm_x4(r, bBase + (uint32_t)nn * (TPAD*2) + kk * 2);
                    b[p*2][0] = r[0]; b[p*2][1] = r[1];
                    b[p*2+1][0] = r[2]; b[p*2+1][1] = r[3];
                }
                #pragma unroll
                for (int mt = 0; mt < 2; mt++)
                    #pragma unroll
                    for (int nt = 0; nt < 4; nt++)
                        mma_bf16(acc[mt][nt], a[mt], b[nt]);
            }
        }
    }

    // ---- epilogue: + bias (+ relu for intermediate layers), store ----
    #pragma unroll
    for (int mt = 0; mt < 2; mt++) {
        int r0 = rowBase + mW + mt * 16 + (lane >> 2);
        int r1 = r0 + 8;
        #pragma unroll
        for (int nt = 0; nt < 4; nt++) {
            int col = nW + nt * 8 + (lane & 3) * 2;
            float b0 = bias[col], b1 = bias[col + 1];
            float v00 = acc[mt][nt][0] + b0, v01 = acc[mt][nt][1] + b1;
            float v10 = acc[mt][nt][2] + b0, v11 = acc[mt][nt][3] + b1;
            if (reluStore) {
                v00 = fmaxf(v00, 0.f); v01 = fmaxf(v01, 0.f);
                v10 = fmaxf(v10, 0.f); v11 = fmaxf(v11, 0.f);
            }
            if (r0 < N_NODES)
                *(float2*)(out + (size_t)r0 * HID + col) = make_float2(v00, v01);
            if (r1 < N_NODES)
                *(float2*)(out + (size_t)r1 * HID + col) = make_float2(v10, v11);
        }
    }
}

// ================= launch ================================================
extern "C" void kernel_launch(void* const* d_in, const int* in_sizes, int n_in,
                              void* d_out, int out_size)
{
    const int*   edge_index = (const int*)d_in[0];
    const int*   edge_type  = (const int*)d_in[1];
    const float* node_init  = (const float*)d_in[2];
    const float* W          = (const float*)d_in[3];
    const float* root       = (const float*)d_in[4];
    const float* bias       = (const float*)d_in[5];
    float*       out        = (float*)d_out;

    void* p;
    cudaGetSymbolAddress(&p, g_bufA); float* bufA = (float*)p;
    cudaGetSymbolAddress(&p, g_bufB); float* bufB = (float*)p;
    cudaGetSymbolAddress(&p, g_whi);  __nv_bfloat16* whi = (__nv_bfloat16*)p;
    cudaGetSymbolAddress(&p, g_wlo);  __nv_bfloat16* wlo = (__nv_bfloat16*)p;

    cudaFuncSetAttribute(rgcn_gemm,
                         cudaFuncAttributeMaxDynamicSharedMemorySize, SM_TOTAL);

    const int scanBlocks = (NSEG + 1023) / 1024;   // 782
    prep0_kernel<<<(W_ELEMS + 255) / 256, 256>>>(W, root);
    prep_edges_kernel<<<(N_EDGES + 255) / 256, 256>>>(edge_index, edge_type);
    scan1_kernel<<<scanBlocks, 256>>>();
    scan2_kernel<<<1, 256>>>(scanBlocks);
    bin_edges_kernel<<<(N_EDGES + 255) / 256, 256>>>();

    const int rowTiles = (N_NODES + 127) / 128;    // 391
    const float* xin = node_init;

    for (int l = 0; l < N_LAYERS; l++) {
        float* xout = (l == N_LAYERS - 1) ? out : (l == 0 ? bufA : bufB);
        int reluStore = (l < N_LAYERS - 1) ? 1 : 0;
        agg_kernel<<<NSEG / 8, 256>>>(xin);
        rgcn_gemm<<<rowTiles, 512, SM_TOTAL>>>(
            xin, whi + (size_t)l * NCHUNK * 16384, wlo + (size_t)l * NCHUNK * 16384,
            bias + (size_t)l * HID, xout, reluStore);
        xin = xout;
    }
}

// round 11
// speedup vs baseline: 1.8936x; 1.4660x over previous
#include <cuda_runtime.h>
#include <cuda_fp16.h>
#include <cstdint>

#define N_NODES  50000
#define N_REL    16
#define HID      128
#define N_LAYERS 3
#define N_EDGES  1600000
#define NSEG     (N_NODES * N_REL)   // 800000
#define KTOT     (N_REL * HID)       // 2048
#define NCHUNK   (N_REL + 1)         // 16 relations + root
#define W_ELEMS  (N_LAYERS * NCHUNK * 16384)

// ================= device scratch (no cudaMalloc allowed) =================
__device__ __align__(16) __half g_agg[(size_t)N_NODES * KTOT];   // 204.8 MB fp16
__device__ __align__(16) float g_bufA[(size_t)N_NODES * HID];
__device__ __align__(16) float g_bufB[(size_t)N_NODES * HID];
// weight stack: per layer 17 tiles of [n][k] fp16 (16 relations + root)
// whi = fp16(W); wlo = fp16((W - whi) * 2048)  (scaled to avoid fp16 denormals)
__device__ __align__(16) __half g_whi[(size_t)W_ELEMS];
__device__ __align__(16) __half g_wlo[(size_t)W_ELEMS];
__device__ int g_cnt[NSEG];
__device__ int g_segstart[NSEG];  // block-local scan (finalize with blkoff)
__device__ int g_cursor[NSEG];
__device__ int g_blksum[1024];
__device__ int g_blkoff[1024];
__device__ int g_eseg[N_EDGES];
__device__ int g_esrc[N_EDGES];
__device__ int g_srcSorted[N_EDGES];

// ================= helpers =================
__device__ __forceinline__ uint32_t smem_to_u32(const void* p) {
    uint32_t a;
    asm("{ .reg .u64 t; cvta.to.shared.u64 t, %1; cvt.u32.u64 %0, t; }"
        : "=r"(a) : "l"(p));
    return a;
}
__device__ __forceinline__ void ldsm_x4(uint32_t* r, uint32_t addr) {
    asm volatile("ldmatrix.sync.aligned.m8n8.x4.shared.b16 {%0,%1,%2,%3}, [%4];"
        : "=r"(r[0]), "=r"(r[1]), "=r"(r[2]), "=r"(r[3]) : "r"(addr));
}
__device__ __forceinline__ void mma_f16(float* d, const uint32_t* a, const uint32_t* b) {
    asm volatile("mma.sync.aligned.m16n8k16.row.col.f32.f16.f16.f32 "
        "{%0,%1,%2,%3}, {%4,%5,%6,%7}, {%8,%9}, {%0,%1,%2,%3};"
        : "+f"(d[0]), "+f"(d[1]), "+f"(d[2]), "+f"(d[3])
        : "r"(a[0]), "r"(a[1]), "r"(a[2]), "r"(a[3]), "r"(b[0]), "r"(b[1]));
}

// ================= prep (5 launches) =======================================
__global__ void prep0_kernel(const float* __restrict__ W,
                             const float* __restrict__ root) {
    int t = blockIdx.x * blockDim.x + threadIdx.x;
    if (t < NSEG) { g_cnt[t] = 0; g_cursor[t] = 0; }
    if (t < W_ELEMS) {
        int tt  = t >> 14;
        int rem = t & 16383;
        int n = rem >> 7;
        int k = rem & 127;
        int l = tt / NCHUNK;
        int c = tt % NCHUNK;
        float v;
        if (c < N_REL) v = W[(((size_t)l * N_REL + c) * HID + k) * HID + n];
        else           v = root[((size_t)l * HID + k) * HID + n];
        __half hi = __float2half_rn(v);
        __half lo = __float2half_rn((v - __half2float(hi)) * 2048.0f);
        size_t off = (size_t)tt * 16384 + n * HID + k;
        g_whi[off] = hi;
        g_wlo[off] = lo;
    }
}
__global__ void prep_edges_kernel(const int* __restrict__ edge_index,
                                  const int* __restrict__ edge_type) {
    int e = blockIdx.x * blockDim.x + threadIdx.x;
    if (e >= N_EDGES) return;
    int s = edge_index[e];
    int t = edge_index[N_EDGES + e];
    int r = edge_type[e];
    if ((unsigned)s >= N_NODES || (unsigned)t >= N_NODES || (unsigned)r >= N_REL) {
        g_eseg[e] = -1; g_esrc[e] = 0; return;
    }
    g_eseg[e] = t * N_REL + r;
    g_esrc[e] = s;
    atomicAdd(&g_cnt[t * N_REL + r], 1);
}
__global__ void scan1_kernel() {
    __shared__ int s[256];
    int base = blockIdx.x * 1024;
    int t = threadIdx.x;
    int v[4]; int sum = 0;
    #pragma unroll
    for (int j = 0; j < 4; j++) {
        int idx = base + t * 4 + j;
        v[j] = (idx < NSEG) ? g_cnt[idx] : 0;
        sum += v[j];
    }
    s[t] = sum; __syncthreads();
    for (int off = 1; off < 256; off <<= 1) {
        int x = 0;
        if (t >= off) x = s[t - off];
        __syncthreads();
        if (t >= off) s[t] += x;
        __syncthreads();
    }
    int excl = (t > 0) ? s[t - 1] : 0;
    if (t == 255) g_blksum[blockIdx.x] = s[255];
    int run = excl;
    #pragma unroll
    for (int j = 0; j < 4; j++) {
        int idx = base + t * 4 + j;
        if (idx < NSEG) g_segstart[idx] = run;
        run += v[j];
    }
}
__global__ void scan2_kernel(int nb) {
    __shared__ int s[256];
    int t = threadIdx.x;
    int v[4]; int sum = 0;
    #pragma unroll
    for (int j = 0; j < 4; j++) {
        int idx = t * 4 + j;
        v[j] = (idx < nb) ? g_blksum[idx] : 0;
        sum += v[j];
    }
    s[t] = sum; __syncthreads();
    for (int off = 1; off < 256; off <<= 1) {
        int x = 0;
        if (t >= off) x = s[t - off];
        __syncthreads();
        if (t >= off) s[t] += x;
        __syncthreads();
    }
    int excl = (t > 0) ? s[t - 1] : 0;
    int run = excl;
    #pragma unroll
    for (int j = 0; j < 4; j++) {
        int idx = t * 4 + j;
        if (idx < nb) g_blkoff[idx] = run;
        run += v[j];
    }
}
__global__ void bin_edges_kernel() {
    int e = blockIdx.x * blockDim.x + threadIdx.x;
    if (e >= N_EDGES) return;
    int seg = g_eseg[e];
    if (seg < 0) return;
    int base = g_segstart[seg] + g_blkoff[seg >> 10];
    int pos = base + atomicAdd(&g_cursor[seg], 1);
    g_srcSorted[pos] = g_esrc[e];
}

// ================= full-range aggregation (no atomics) =====================
// One warp per (node,rel) segment. x is pre-activated. Single fp16 output,
// streaming store (.cs) — write-once data, keep L2 for x.
__global__ __launch_bounds__(256) void agg_kernel(const float* __restrict__ x)
{
    int w = (blockIdx.x * 256 + threadIdx.x) >> 5;
    int lane = threadIdx.x & 31;
    if (w >= NSEG) return;
    int st = g_segstart[w] + g_blkoff[w >> 10];
    int c  = g_cnt[w];
    float4 sum = make_float4(0.f, 0.f, 0.f, 0.f);
    for (int i = 0; i < c; i++) {
        int s = __ldg(g_srcSorted + st + i);
        float4 v = __ldg((const float4*)(x + (size_t)s * HID) + lane);
        sum.x += v.x; sum.y += v.y; sum.z += v.z; sum.w += v.w;
    }
    float inv = (c > 0) ? 1.0f / (float)c : 0.0f;
    sum.x *= inv; sum.y *= inv; sum.z *= inv; sum.w *= inv;

    __half2 p0 = __floats2half2_rn(sum.x, sum.y);
    __half2 p1 = __floats2half2_rn(sum.z, sum.w);
    size_t off = (size_t)w * HID + lane * 4;   // seg*128 = node*2048 + rel*128
    asm volatile("st.global.cs.v2.b32 [%0], {%1,%2};"
                 :: "l"(g_agg + off), "r"(*(uint32_t*)&p0), "r"(*(uint32_t*)&p1)
                 : "memory");
}

// ================= layer GEMM: out = [agg | x] @ [Wstk; root] + bias =======
// K = 17 chunks x 128. 512 threads / 16 warps (32x32 warp tiles).
// 2 MMA terms: acc1 = A*Bhi, acc2 = A*(Blo*2048); out = acc1 + acc2/2048.
#define TPAD      136
#define TILE_B    (128 * TPAD * 2)           // 34816 bytes
#define SM_A      0
#define SM_BHI    (SM_A + TILE_B)
#define SM_BLO    (SM_BHI + TILE_B)
#define SM_TOTAL  (SM_BLO + TILE_B)          // 104448

__global__ __launch_bounds__(512) void rgcn_gemm(
    const float* __restrict__ xin,
    const __half* __restrict__ whi,          // layer's 17-tile stack
    const __half* __restrict__ wlo,
    const float* __restrict__ bias,
    float* __restrict__ out, int reluStore)
{
    extern __shared__ __align__(16) char smem[];
    const uint32_t sb = smem_to_u32(smem);
    const int tid  = threadIdx.x;
    const int wid  = tid >> 5;
    const int lane = tid & 31;
    const int rowBase = blockIdx.x * 128;

    const int mW = (wid & 3) * 32;
    const int nW = (wid >> 2) * 32;

    float acc1[2][4][4], acc2[2][4][4];
    #pragma unroll
    for (int mt = 0; mt < 2; mt++)
        #pragma unroll
        for (int nt = 0; nt < 4; nt++)
            #pragma unroll
            for (int q = 0; q < 4; q++) { acc1[mt][nt][q] = 0.0f; acc2[mt][nt][q] = 0.0f; }

    for (int kc = 0; kc < NCHUNK; kc++) {
        __syncthreads();   // prior chunk's ldsm reads complete
        // ---- A chunk ----
        if (kc < N_REL) {
            // fp16 agg chunk (streamed, read-once): 4 fl4/thread
            #pragma unroll
            for (int i = 0; i < 4; i++) {
                int idx4 = tid + i * 512;        // 0..2047
                int row = idx4 >> 4, c16 = idx4 & 15;
                int gr = rowBase + row;
                float4 v = make_float4(0.f,0.f,0.f,0.f);
                if (gr < N_NODES) {
                    size_t o = (size_t)gr * KTOT + kc * HID + c16 * 8;
                    v = __ldcs((const float4*)(g_agg + o));
                }
                *(float4*)(smem + SM_A + row * (TPAD*2) + c16 * 16) = v;
            }
        } else {
            // root chunk: fp32 x (pre-activated) -> fp16 (8 fl4/thread)
            #pragma unroll
            for (int i = 0; i < 8; i++) {
                int idx4 = tid + i * 512;        // 0..4095
                int row = idx4 >> 5, kq = (idx4 & 31) << 2;
                int gr = rowBase + row;
                float4 v = make_float4(0.f,0.f,0.f,0.f);
                if (gr < N_NODES) v = *(const float4*)(xin + (size_t)gr * HID + kq);
                __half2 p0 = __floats2half2_rn(v.x, v.y);
                __half2 p1 = __floats2half2_rn(v.z, v.w);
                uint2 P; P.x = *(uint32_t*)&p0; P.y = *(uint32_t*)&p1;
                *(uint2*)(smem + SM_A + row * (TPAD*2) + kq * 2) = P;
            }
        }
        // ---- B chunk (L2-resident weight stack), 4 fl4/thread ----
        {
            const __half* bh = whi + (size_t)kc * 16384;
            const __half* bl = wlo + (size_t)kc * 16384;
            #pragma unroll
            for (int i = 0; i < 4; i++) {
                int idx4 = tid + i * 512;        // 0..2047
                int row = idx4 >> 4, c16 = idx4 & 15;
                *(float4*)(smem + SM_BHI + row * (TPAD*2) + c16 * 16) =
                    *(const float4*)(bh + row * HID + c16 * 8);
                *(float4*)(smem + SM_BLO + row * (TPAD*2) + c16 * 16) =
                    *(const float4*)(bl + row * HID + c16 * 8);
            }
        }
        __syncthreads();

        // ---- MMA: A shared by both B terms ----
        #pragma unroll
        for (int k0 = 0; k0 < HID; k0 += 16) {
            uint32_t a[2][4];
            {
                int ar = mW + (lane & 15);
                int ac = k0 + ((lane >> 4) << 3);
                ldsm_x4(a[0], sb + SM_A + (uint32_t)ar * (TPAD*2) + ac * 2);
                ldsm_x4(a[1], sb + SM_A + (uint32_t)(ar + 16) * (TPAD*2) + ac * 2);
            }
            uint32_t bh[4][2], bl[4][2];
            #pragma unroll
            for (int p = 0; p < 2; p++) {
                int g  = lane >> 3;
                int nn = nW + p * 16 + (lane & 7) + ((g >> 1) << 3);
                int kk = k0 + ((g & 1) << 3);
                uint32_t r[4];
                ldsm_x4(r, sb + SM_BHI + (uint32_t)nn * (TPAD*2) + kk * 2);
                bh[p*2][0] = r[0]; bh[p*2][1] = r[1];
                bh[p*2+1][0] = r[2]; bh[p*2+1][1] = r[3];
                ldsm_x4(r, sb + SM_BLO + (uint32_t)nn * (TPAD*2) + kk * 2);
                bl[p*2][0] = r[0]; bl[p*2][1] = r[1];
                bl[p*2+1][0] = r[2]; bl[p*2+1][1] = r[3];
            }
            #pragma unroll
            for (int mt = 0; mt < 2; mt++)
                #pragma unroll
                for (int nt = 0; nt < 4; nt++) {
                    mma_f16(acc1[mt][nt], a[mt], bh[nt]);
                    mma_f16(acc2[mt][nt], a[mt], bl[nt]);
                }
        }
    }

    // ---- epilogue: fold scaled-lo term, + bias (+ relu), store ----
    const float INV2048 = 1.0f / 2048.0f;
    #pragma unroll
    for (int mt = 0; mt < 2; mt++) {
        int r0 = rowBase + mW + mt * 16 + (lane >> 2);
        int r1 = r0 + 8;
        #pragma unroll
        for (int nt = 0; nt < 4; nt++) {
            int col = nW + nt * 8 + (lane & 3) * 2;
            float b0 = bias[col], b1 = bias[col + 1];
            float v00 = acc1[mt][nt][0] + acc2[mt][nt][0] * INV2048 + b0;
            float v01 = acc1[mt][nt][1] + acc2[mt][nt][1] * INV2048 + b1;
            float v10 = acc1[mt][nt][2] + acc2[mt][nt][2] * INV2048 + b0;
            float v11 = acc1[mt][nt][3] + acc2[mt][nt][3] * INV2048 + b1;
            if (reluStore) {
                v00 = fmaxf(v00, 0.f); v01 = fmaxf(v01, 0.f);
                v10 = fmaxf(v10, 0.f); v11 = fmaxf(v11, 0.f);
            }
            if (r0 < N_NODES)
                *(float2*)(out + (size_t)r0 * HID + col) = make_float2(v00, v01);
            if (r1 < N_NODES)
                *(float2*)(out + (size_t)r1 * HID + col) = make_float2(v10, v11);
        }
    }
}

// ================= launch ================================================
extern "C" void kernel_launch(void* const* d_in, const int* in_sizes, int n_in,
                              void* d_out, int out_size)
{
    const int*   edge_index = (const int*)d_in[0];
    const int*   edge_type  = (const int*)d_in[1];
    const float* node_init  = (const float*)d_in[2];
    const float* W          = (const float*)d_in[3];
    const float* root       = (const float*)d_in[4];
    const float* bias       = (const float*)d_in[5];
    float*       out        = (float*)d_out;

    void* p;
    cudaGetSymbolAddress(&p, g_bufA); float* bufA = (float*)p;
    cudaGetSymbolAddress(&p, g_bufB); float* bufB = (float*)p;
    cudaGetSymbolAddress(&p, g_whi);  __half* whi = (__half*)p;
    cudaGetSymbolAddress(&p, g_wlo);  __half* wlo = (__half*)p;

    cudaFuncSetAttribute(rgcn_gemm,
                         cudaFuncAttributeMaxDynamicSharedMemorySize, SM_TOTAL);

    const int scanBlocks = (NSEG + 1023) / 1024;   // 782
    prep0_kernel<<<(W_ELEMS + 255) / 256, 256>>>(W, root);
    prep_edges_kernel<<<(N_EDGES + 255) / 256, 256>>>(edge_index, edge_type);
    scan1_kernel<<<scanBlocks, 256>>>();
    scan2_kernel<<<1, 256>>>(scanBlocks);
    bin_edges_kernel<<<(N_EDGES + 255) / 256, 256>>>();

    const int rowTiles = (N_NODES + 127) / 128;    // 391
    const float* xin = node_init;

    for (int l = 0; l < N_LAYERS; l++) {
        float* xout = (l == N_LAYERS - 1) ? out : (l == 0 ? bufA : bufB);
        int reluStore = (l < N_LAYERS - 1) ? 1 : 0;
        agg_kernel<<<NSEG / 8, 256>>>(xin);
        rgcn_gemm<<<rowTiles, 512, SM_TOTAL>>>(
            xin, whi + (size_t)l * NCHUNK * 16384, wlo + (size_t)l * NCHUNK * 16384,
            bias + (size_t)l * HID, xout, reluStore);
        xin = xout;
    }
}

// round 12
// speedup vs baseline: 2.3971x; 1.2659x over previous
#include <cuda_runtime.h>
#include <cuda_fp16.h>
#include <cstdint>

#define N_NODES  50000
#define N_REL    16
#define HID      128
#define N_LAYERS 3
#define N_EDGES  1600000
#define NSEG     (N_NODES * N_REL)   // 800000
#define KTOT     (N_REL * HID)       // 2048
#define NCHUNK   (N_REL + 1)         // 16 relations + root
#define W_ELEMS  (N_LAYERS * NCHUNK * 16384)

// ================= device scratch (no cudaMalloc allowed) =================
__device__ __align__(16) __half g_agg[(size_t)N_NODES * KTOT];   // 204.8 MB fp16
__device__ __align__(16) float g_bufA[(size_t)N_NODES * HID];
__device__ __align__(16) float g_bufB[(size_t)N_NODES * HID];
// weight stack: per layer 17 tiles of [n][k] fp16 (16 relations + root)
__device__ __align__(16) __half g_w[(size_t)W_ELEMS];
__device__ int g_cnt[NSEG];
__device__ int g_segstart[NSEG];  // block-local scan (finalize with blkoff)
__device__ int g_cursor[NSEG];
__device__ int g_blksum[1024];
__device__ int g_blkoff[1024];
__device__ int g_eseg[N_EDGES];
__device__ int g_esrc[N_EDGES];
__device__ int g_srcSorted[N_EDGES];

// ================= helpers =================
__device__ __forceinline__ uint32_t smem_to_u32(const void* p) {
    uint32_t a;
    asm("{ .reg .u64 t; cvta.to.shared.u64 t, %1; cvt.u32.u64 %0, t; }"
        : "=r"(a) : "l"(p));
    return a;
}
__device__ __forceinline__ void ldsm_x4(uint32_t* r, uint32_t addr) {
    asm volatile("ldmatrix.sync.aligned.m8n8.x4.shared.b16 {%0,%1,%2,%3}, [%4];"
        : "=r"(r[0]), "=r"(r[1]), "=r"(r[2]), "=r"(r[3]) : "r"(addr));
}
__device__ __forceinline__ void mma_f16(float* d, const uint32_t* a, const uint32_t* b) {
    asm volatile("mma.sync.aligned.m16n8k16.row.col.f32.f16.f16.f32 "
        "{%0,%1,%2,%3}, {%4,%5,%6,%7}, {%8,%9}, {%0,%1,%2,%3};"
        : "+f"(d[0]), "+f"(d[1]), "+f"(d[2]), "+f"(d[3])
        : "r"(a[0]), "r"(a[1]), "r"(a[2]), "r"(a[3]), "r"(b[0]), "r"(b[1]));
}

// ================= prep (5 launches) =======================================
__global__ void prep0_kernel(const float* __restrict__ W,
                             const float* __restrict__ root) {
    int t = blockIdx.x * blockDim.x + threadIdx.x;
    if (t < NSEG) { g_cnt[t] = 0; g_cursor[t] = 0; }
    if (t < W_ELEMS) {
        int tt  = t >> 14;
        int rem = t & 16383;
        int n = rem >> 7;
        int k = rem & 127;
        int l = tt / NCHUNK;
        int c = tt % NCHUNK;
        float v;
        if (c < N_REL) v = W[(((size_t)l * N_REL + c) * HID + k) * HID + n];
        else           v = root[((size_t)l * HID + k) * HID + n];
        g_w[(size_t)tt * 16384 + n * HID + k] = __float2half_rn(v);
    }
}
__global__ void prep_edges_kernel(const int* __restrict__ edge_index,
                                  const int* __restrict__ edge_type) {
    int e = blockIdx.x * blockDim.x + threadIdx.x;
    if (e >= N_EDGES) return;
    int s = edge_index[e];
    int t = edge_index[N_EDGES + e];
    int r = edge_type[e];
    if ((unsigned)s >= N_NODES || (unsigned)t >= N_NODES || (unsigned)r >= N_REL) {
        g_eseg[e] = -1; g_esrc[e] = 0; return;
    }
    g_eseg[e] = t * N_REL + r;
    g_esrc[e] = s;
    atomicAdd(&g_cnt[t * N_REL + r], 1);
}
__global__ void scan1_kernel() {
    __shared__ int s[256];
    int base = blockIdx.x * 1024;
    int t = threadIdx.x;
    int v[4]; int sum = 0;
    #pragma unroll
    for (int j = 0; j < 4; j++) {
        int idx = base + t * 4 + j;
        v[j] = (idx < NSEG) ? g_cnt[idx] : 0;
        sum += v[j];
    }
    s[t] = sum; __syncthreads();
    for (int off = 1; off < 256; off <<= 1) {
        int x = 0;
        if (t >= off) x = s[t - off];
        __syncthreads();
        if (t >= off) s[t] += x;
        __syncthreads();
    }
    int excl = (t > 0) ? s[t - 1] : 0;
    if (t == 255) g_blksum[blockIdx.x] = s[255];
    int run = excl;
    #pragma unroll
    for (int j = 0; j < 4; j++) {
        int idx = base + t * 4 + j;
        if (idx < NSEG) g_segstart[idx] = run;
        run += v[j];
    }
}
__global__ void scan2_kernel(int nb) {
    __shared__ int s[256];
    int t = threadIdx.x;
    int v[4]; int sum = 0;
    #pragma unroll
    for (int j = 0; j < 4; j++) {
        int idx = t * 4 + j;
        v[j] = (idx < nb) ? g_blksum[idx] : 0;
        sum += v[j];
    }
    s[t] = sum; __syncthreads();
    for (int off = 1; off < 256; off <<= 1) {
        int x = 0;
        if (t >= off) x = s[t - off];
        __syncthreads();
        if (t >= off) s[t] += x;
        __syncthreads();
    }
    int excl = (t > 0) ? s[t - 1] : 0;
    int run = excl;
    #pragma unroll
    for (int j = 0; j < 4; j++) {
        int idx = t * 4 + j;
        if (idx < nb) g_blkoff[idx] = run;
        run += v[j];
    }
}
__global__ void bin_edges_kernel() {
    int e = blockIdx.x * blockDim.x + threadIdx.x;
    if (e >= N_EDGES) return;
    int seg = g_eseg[e];
    if (seg < 0) return;
    int base = g_segstart[seg] + g_blkoff[seg >> 10];
    int pos = base + atomicAdd(&g_cursor[seg], 1);
    g_srcSorted[pos] = g_esrc[e];
}

// ================= full-range aggregation (no atomics) =====================
// One warp per (node,rel) segment. x is pre-activated. Single fp16 output,
// streaming store (.cs) — write-once data, keep L2 for x.
__global__ __launch_bounds__(256) void agg_kernel(const float* __restrict__ x)
{
    int w = (blockIdx.x * 256 + threadIdx.x) >> 5;
    int lane = threadIdx.x & 31;
    if (w >= NSEG) return;
    int st = g_segstart[w] + g_blkoff[w >> 10];
    int c  = g_cnt[w];
    float4 sum = make_float4(0.f, 0.f, 0.f, 0.f);
    for (int i = 0; i < c; i++) {
        int s = __ldg(g_srcSorted + st + i);
        float4 v = __ldg((const float4*)(x + (size_t)s * HID) + lane);
        sum.x += v.x; sum.y += v.y; sum.z += v.z; sum.w += v.w;
    }
    float inv = (c > 0) ? 1.0f / (float)c : 0.0f;
    sum.x *= inv; sum.y *= inv; sum.z *= inv; sum.w *= inv;

    __half2 p0 = __floats2half2_rn(sum.x, sum.y);
    __half2 p1 = __floats2half2_rn(sum.z, sum.w);
    size_t off = (size_t)w * HID + lane * 4;   // seg*128 = node*2048 + rel*128
    asm volatile("st.global.cs.v2.b32 [%0], {%1,%2};"
                 :: "l"(g_agg + off), "r"(*(uint32_t*)&p0), "r"(*(uint32_t*)&p1)
                 : "memory");
}

// ================= layer GEMM: out = [agg | x] @ [Wstk; root] + bias =======
// K = 17 chunks x 128. 512 threads / 16 warps (32x32 warp tiles).
// Single fp16 MMA term; 2 CTAs/SM (68KB smem).
#define TPAD      136
#define TILE_B    (128 * TPAD * 2)           // 34816 bytes
#define SM_A      0
#define SM_B      (SM_A + TILE_B)
#define SM_TOTAL  (SM_B + TILE_B)            // 69632

__global__ __launch_bounds__(512, 2) void rgcn_gemm(
    const float* __restrict__ xin,
    const __half* __restrict__ w,            // layer's 17-tile stack
    const float* __restrict__ bias,
    float* __restrict__ out, int reluStore)
{
    extern __shared__ __align__(16) char smem[];
    const uint32_t sb = smem_to_u32(smem);
    const int tid  = threadIdx.x;
    const int wid  = tid >> 5;
    const int lane = tid & 31;
    const int rowBase = blockIdx.x * 128;

    const int mW = (wid & 3) * 32;
    const int nW = (wid >> 2) * 32;

    float acc[2][4][4];
    #pragma unroll
    for (int mt = 0; mt < 2; mt++)
        #pragma unroll
        for (int nt = 0; nt < 4; nt++)
            #pragma unroll
            for (int q = 0; q < 4; q++) acc[mt][nt][q] = 0.0f;

    for (int kc = 0; kc < NCHUNK; kc++) {
        __syncthreads();   // prior chunk's ldsm reads complete
        // ---- A chunk ----
        if (kc < N_REL) {
            // fp16 agg chunk (streamed, read-once): 4 fl4/thread
            #pragma unroll
            for (int i = 0; i < 4; i++) {
                int idx4 = tid + i * 512;        // 0..2047
                int row = idx4 >> 4, c16 = idx4 & 15;
                int gr = rowBase + row;
                float4 v = make_float4(0.f,0.f,0.f,0.f);
                if (gr < N_NODES) {
                    size_t o = (size_t)gr * KTOT + kc * HID + c16 * 8;
                    v = __ldcs((const float4*)(g_agg + o));
                }
                *(float4*)(smem + SM_A + row * (TPAD*2) + c16 * 16) = v;
            }
        } else {
            // root chunk: fp32 x (pre-activated) -> fp16 (8 fl4/thread)
            #pragma unroll
            for (int i = 0; i < 8; i++) {
                int idx4 = tid + i * 512;        // 0..4095
                int row = idx4 >> 5, kq = (idx4 & 31) << 2;
                int gr = rowBase + row;
                float4 v = make_float4(0.f,0.f,0.f,0.f);
                if (gr < N_NODES) v = *(const float4*)(xin + (size_t)gr * HID + kq);
                __half2 p0 = __floats2half2_rn(v.x, v.y);
                __half2 p1 = __floats2half2_rn(v.z, v.w);
                uint2 P; P.x = *(uint32_t*)&p0; P.y = *(uint32_t*)&p1;
                *(uint2*)(smem + SM_A + row * (TPAD*2) + kq * 2) = P;
            }
        }
        // ---- B chunk (L2-resident weight stack), 2 fl4/thread ----
        {
            const __half* bw = w + (size_t)kc * 16384;
            #pragma unroll
            for (int i = 0; i < 4; i++) {
                int idx4 = tid + i * 512;        // 0..2047
                int row = idx4 >> 4, c16 = idx4 & 15;
                *(float4*)(smem + SM_B + row * (TPAD*2) + c16 * 16) =
                    *(const float4*)(bw + row * HID + c16 * 8);
            }
        }
        __syncthreads();

        // ---- MMA over this 128-K chunk ----
        #pragma unroll
        for (int k0 = 0; k0 < HID; k0 += 16) {
            uint32_t a[2][4];
            {
                int ar = mW + (lane & 15);
                int ac = k0 + ((lane >> 4) << 3);
                ldsm_x4(a[0], sb + SM_A + (uint32_t)ar * (TPAD*2) + ac * 2);
                ldsm_x4(a[1], sb + SM_A + (uint32_t)(ar + 16) * (TPAD*2) + ac * 2);
            }
            uint32_t b[4][2];
            #pragma unroll
            for (int p = 0; p < 2; p++) {
                int g  = lane >> 3;
                int nn = nW + p * 16 + (lane & 7) + ((g >> 1) << 3);
                int kk = k0 + ((g & 1) << 3);
                uint32_t r[4];
                ldsm_x4(r, sb + SM_B + (uint32_t)nn * (TPAD*2) + kk * 2);
                b[p*2][0] = r[0]; b[p*2][1] = r[1];
                b[p*2+1][0] = r[2]; b[p*2+1][1] = r[3];
            }
            #pragma unroll
            for (int mt = 0; mt < 2; mt++)
                #pragma unroll
                for (int nt = 0; nt < 4; nt++)
                    mma_f16(acc[mt][nt], a[mt], b[nt]);
        }
    }

    // ---- epilogue: + bias (+ relu), store ----
    #pragma unroll
    for (int mt = 0; mt < 2; mt++) {
        int r0 = rowBase + mW + mt * 16 + (lane >> 2);
        int r1 = r0 + 8;
        #pragma unroll
        for (int nt = 0; nt < 4; nt++) {
            int col = nW + nt * 8 + (lane & 3) * 2;
            float b0 = bias[col], b1 = bias[col + 1];
            float v00 = acc[mt][nt][0] + b0, v01 = acc[mt][nt][1] + b1;
            float v10 = acc[mt][nt][2] + b0, v11 = acc[mt][nt][3] + b1;
            if (reluStore) {
                v00 = fmaxf(v00, 0.f); v01 = fmaxf(v01, 0.f);
                v10 = fmaxf(v10, 0.f); v11 = fmaxf(v11, 0.f);
            }
            if (r0 < N_NODES)
                *(float2*)(out + (size_t)r0 * HID + col) = make_float2(v00, v01);
            if (r1 < N_NODES)
                *(float2*)(out + (size_t)r1 * HID + col) = make_float2(v10, v11);
        }
    }
}

// ================= launch ================================================
extern "C" void kernel_launch(void* const* d_in, const int* in_sizes, int n_in,
                              void* d_out, int out_size)
{
    const int*   edge_index = (const int*)d_in[0];
    const int*   edge_type  = (const int*)d_in[1];
    const float* node_init  = (const float*)d_in[2];
    const float* W          = (const float*)d_in[3];
    const float* root       = (const float*)d_in[4];
    const float* bias       = (const float*)d_in[5];
    float*       out        = (float*)d_out;

    void* p;
    cudaGetSymbolAddress(&p, g_bufA); float* bufA = (float*)p;
    cudaGetSymbolAddress(&p, g_bufB); float* bufB = (float*)p;
    cudaGetSymbolAddress(&p, g_w);    __half* w   = (__half*)p;

    cudaFuncSetAttribute(rgcn_gemm,
                         cudaFuncAttributeMaxDynamicSharedMemorySize, SM_TOTAL);

    const int scanBlocks = (NSEG + 1023) / 1024;   // 782
    prep0_kernel<<<(W_ELEMS + 255) / 256, 256>>>(W, root);
    prep_edges_kernel<<<(N_EDGES + 255) / 256, 256>>>(edge_index, edge_type);
    scan1_kernel<<<scanBlocks, 256>>>();
    scan2_kernel<<<1, 256>>>(scanBlocks);
    bin_edges_kernel<<<(N_EDGES + 255) / 256, 256>>>();

    const int rowTiles = (N_NODES + 127) / 128;    // 391
    const float* xin = node_init;

    for (int l = 0; l < N_LAYERS; l++) {
        float* xout = (l == N_LAYERS - 1) ? out : (l == 0 ? bufA : bufB);
        int reluStore = (l < N_LAYERS - 1) ? 1 : 0;
        agg_kernel<<<NSEG / 8, 256>>>(xin);
        rgcn_gemm<<<rowTiles, 512, SM_TOTAL>>>(
            xin, w + (size_t)l * NCHUNK * 16384,
            bias + (size_t)l * HID, xout, reluStore);
        xin = xout;
    }
}

// round 13
// speedup vs baseline: 2.4803x; 1.0347x over previous
#include <cuda_runtime.h>
#include <cuda_fp16.h>
#include <cstdint>

#define N_NODES  50000
#define N_REL    16
#define HID      128
#define N_LAYERS 3
#define N_EDGES  1600000
#define NSEG     (N_NODES * N_REL)   // 800000
#define KTOT     (N_REL * HID)       // 2048
#define NCHUNK   (N_REL + 1)         // 16 relations + root
#define W_ELEMS  (N_LAYERS * NCHUNK * 16384)
#define X_ELEMS  (N_NODES * HID)     // 6.4M

// ================= device scratch (no cudaMalloc allowed) =================
__device__ __align__(16) __half g_agg[(size_t)N_NODES * KTOT];   // 204.8 MB fp16
__device__ __align__(16) __half g_xh0[(size_t)X_ELEMS];  // fp16 node_init
__device__ __align__(16) __half g_xhA[(size_t)X_ELEMS];  // fp16 layer outputs
__device__ __align__(16) __half g_xhB[(size_t)X_ELEMS];
// weight stack: per layer 17 tiles of [n][k] fp16 (16 relations + root)
__device__ __align__(16) __half g_w[(size_t)W_ELEMS];
__device__ int g_cnt[NSEG];
__device__ int g_segstart[NSEG];  // block-local scan (finalize with blkoff)
__device__ int g_cursor[NSEG];
__device__ int g_blksum[1024];
__device__ int g_blkoff[1024];
__device__ int g_eseg[N_EDGES];
__device__ int g_esrc[N_EDGES];
__device__ int g_srcSorted[N_EDGES];

// ================= helpers =================
__device__ __forceinline__ uint32_t smem_to_u32(const void* p) {
    uint32_t a;
    asm("{ .reg .u64 t; cvta.to.shared.u64 t, %1; cvt.u32.u64 %0, t; }"
        : "=r"(a) : "l"(p));
    return a;
}
__device__ __forceinline__ void ldsm_x4(uint32_t* r, uint32_t addr) {
    asm volatile("ldmatrix.sync.aligned.m8n8.x4.shared.b16 {%0,%1,%2,%3}, [%4];"
        : "=r"(r[0]), "=r"(r[1]), "=r"(r[2]), "=r"(r[3]) : "r"(addr));
}
__device__ __forceinline__ void mma_f16(float* d, const uint32_t* a, const uint32_t* b) {
    asm volatile("mma.sync.aligned.m16n8k16.row.col.f32.f16.f16.f32 "
        "{%0,%1,%2,%3}, {%4,%5,%6,%7}, {%8,%9}, {%0,%1,%2,%3};"
        : "+f"(d[0]), "+f"(d[1]), "+f"(d[2]), "+f"(d[3])
        : "r"(a[0]), "r"(a[1]), "r"(a[2]), "r"(a[3]), "r"(b[0]), "r"(b[1]));
}

// ================= prep (5 launches) =======================================
// k1: zero counters + convert weights + convert node_init to fp16
__global__ void prep0_kernel(const float* __restrict__ W,
                             const float* __restrict__ root,
                             const float* __restrict__ x0) {
    int t = blockIdx.x * blockDim.x + threadIdx.x;
    if (t < NSEG) { g_cnt[t] = 0; g_cursor[t] = 0; }
    if (t < W_ELEMS) {
        int tt  = t >> 14;
        int rem = t & 16383;
        int n = rem >> 7;
        int k = rem & 127;
        int l = tt / NCHUNK;
        int c = tt % NCHUNK;
        float v;
        if (c < N_REL) v = W[(((size_t)l * N_REL + c) * HID + k) * HID + n];
        else           v = root[((size_t)l * HID + k) * HID + n];
        g_w[(size_t)tt * 16384 + n * HID + k] = __float2half_rn(v);
    }
    if (t < X_ELEMS) g_xh0[t] = __float2half_rn(x0[t]);
}
__global__ void prep_edges_kernel(const int* __restrict__ edge_index,
                                  const int* __restrict__ edge_type) {
    int e = blockIdx.x * blockDim.x + threadIdx.x;
    if (e >= N_EDGES) return;
    int s = edge_index[e];
    int t = edge_index[N_EDGES + e];
    int r = edge_type[e];
    if ((unsigned)s >= N_NODES || (unsigned)t >= N_NODES || (unsigned)r >= N_REL) {
        g_eseg[e] = -1; g_esrc[e] = 0; return;
    }
    g_eseg[e] = t * N_REL + r;
    g_esrc[e] = s;
    atomicAdd(&g_cnt[t * N_REL + r], 1);
}
__global__ void scan1_kernel() {
    __shared__ int s[256];
    int base = blockIdx.x * 1024;
    int t = threadIdx.x;
    int v[4]; int sum = 0;
    #pragma unroll
    for (int j = 0; j < 4; j++) {
        int idx = base + t * 4 + j;
        v[j] = (idx < NSEG) ? g_cnt[idx] : 0;
        sum += v[j];
    }
    s[t] = sum; __syncthreads();
    for (int off = 1; off < 256; off <<= 1) {
        int x = 0;
        if (t >= off) x = s[t - off];
        __syncthreads();
        if (t >= off) s[t] += x;
        __syncthreads();
    }
    int excl = (t > 0) ? s[t - 1] : 0;
    if (t == 255) g_blksum[blockIdx.x] = s[255];
    int run = excl;
    #pragma unroll
    for (int j = 0; j < 4; j++) {
        int idx = base + t * 4 + j;
        if (idx < NSEG) g_segstart[idx] = run;
        run += v[j];
    }
}
__global__ void scan2_kernel(int nb) {
    __shared__ int s[256];
    int t = threadIdx.x;
    int v[4]; int sum = 0;
    #pragma unroll
    for (int j = 0; j < 4; j++) {
        int idx = t * 4 + j;
        v[j] = (idx < nb) ? g_blksum[idx] : 0;
        sum += v[j];
    }
    s[t] = sum; __syncthreads();
    for (int off = 1; off < 256; off <<= 1) {
        int x = 0;
        if (t >= off) x = s[t - off];
        __syncthreads();
        if (t >= off) s[t] += x;
        __syncthreads();
    }
    int excl = (t > 0) ? s[t - 1] : 0;
    int run = excl;
    #pragma unroll
    for (int j = 0; j < 4; j++) {
        int idx = t * 4 + j;
        if (idx < nb) g_blkoff[idx] = run;
        run += v[j];
    }
}
__global__ void bin_edges_kernel() {
    int e = blockIdx.x * blockDim.x + threadIdx.x;
    if (e >= N_EDGES) return;
    int seg = g_eseg[e];
    if (seg < 0) return;
    int base = g_segstart[seg] + g_blkoff[seg >> 10];
    int pos = base + atomicAdd(&g_cursor[seg], 1);
    g_srcSorted[pos] = g_esrc[e];
}

// ================= full-range aggregation (no atomics) =====================
// One warp per (node,rel) segment. x is fp16 + pre-activated: per edge a
// lane reads 8B (4 halfs), accumulates fp32, rounds mean to fp16.
__global__ __launch_bounds__(256) void agg_kernel(const __half* __restrict__ xh)
{
    int w = (blockIdx.x * 256 + threadIdx.x) >> 5;
    int lane = threadIdx.x & 31;
    if (w >= NSEG) return;
    int st = g_segstart[w] + g_blkoff[w >> 10];
    int c  = g_cnt[w];
    float4 sum = make_float4(0.f, 0.f, 0.f, 0.f);
    for (int i = 0; i < c; i++) {
        int s = __ldg(g_srcSorted + st + i);
        uint2 rv = __ldg((const uint2*)(xh + (size_t)s * HID) + lane);
        float2 f0 = __half22float2(*(__half2*)&rv.x);
        float2 f1 = __half22float2(*(__half2*)&rv.y);
        sum.x += f0.x; sum.y += f0.y; sum.z += f1.x; sum.w += f1.y;
    }
    float inv = (c > 0) ? 1.0f / (float)c : 0.0f;
    __half2 p0 = __floats2half2_rn(sum.x * inv, sum.y * inv);
    __half2 p1 = __floats2half2_rn(sum.z * inv, sum.w * inv);
    size_t off = (size_t)w * HID + lane * 4;   // seg*128 = node*2048 + rel*128
    asm volatile("st.global.cs.v2.b32 [%0], {%1,%2};"
                 :: "l"(g_agg + off), "r"(*(uint32_t*)&p0), "r"(*(uint32_t*)&p1)
                 : "memory");
}

// ================= layer GEMM: out = [agg | x] @ [Wstk; root] + bias =======
// K = 17 chunks x 128. 512 threads / 16 warps (32x32 warp tiles).
// Single fp16 MMA term; 2 CTAs/SM (68KB smem). Intermediate layers store
// fp16 (outh); final layer stores fp32 (outf).
#define TPAD      136
#define TILE_B    (128 * TPAD * 2)           // 34816 bytes
#define SM_A      0
#define SM_B      (SM_A + TILE_B)
#define SM_TOTAL  (SM_B + TILE_B)            // 69632

__global__ __launch_bounds__(512, 2) void rgcn_gemm(
    const __half* __restrict__ xh,           // fp16 activations (pre-activated)
    const __half* __restrict__ w,            // layer's 17-tile stack
    const float* __restrict__ bias,
    float* __restrict__ outf,                // final-layer fp32 out (or null)
    __half* __restrict__ outh,               // intermediate fp16 out (or null)
    int reluStore)
{
    extern __shared__ __align__(16) char smem[];
    const uint32_t sb = smem_to_u32(smem);
    const int tid  = threadIdx.x;
    const int wid  = tid >> 5;
    const int lane = tid & 31;
    const int rowBase = blockIdx.x * 128;

    const int mW = (wid & 3) * 32;
    const int nW = (wid >> 2) * 32;

    float acc[2][4][4];
    #pragma unroll
    for (int mt = 0; mt < 2; mt++)
        #pragma unroll
        for (int nt = 0; nt < 4; nt++)
            #pragma unroll
            for (int q = 0; q < 4; q++) acc[mt][nt][q] = 0.0f;

    for (int kc = 0; kc < NCHUNK; kc++) {
        __syncthreads();   // prior chunk's ldsm reads complete
        // ---- A chunk: fp16 rows (agg for kc<16, x for root chunk) ----
        {
            const __half* asrc;
            size_t rowStride;
            if (kc < N_REL) { asrc = g_agg + (size_t)kc * HID; rowStride = KTOT; }
            else            { asrc = xh;                        rowStride = HID;  }
            #pragma unroll
            for (int i = 0; i < 4; i++) {
                int idx4 = tid + i * 512;        // 0..2047
                int row = idx4 >> 4, c16 = idx4 & 15;
                int gr = rowBase + row;
                float4 v = make_float4(0.f,0.f,0.f,0.f);
                if (gr < N_NODES) {
                    const float4* p = (const float4*)(asrc + (size_t)gr * rowStride) + c16;
                    v = (kc < N_REL) ? __ldcs(p) : __ldg(p);
                }
                *(float4*)(smem + SM_A + row * (TPAD*2) + c16 * 16) = v;
            }
        }
        // ---- B chunk (L2-resident weight stack) ----
        {
            const __half* bw = w + (size_t)kc * 16384;
            #pragma unroll
            for (int i = 0; i < 4; i++) {
                int idx4 = tid + i * 512;        // 0..2047
                int row = idx4 >> 4, c16 = idx4 & 15;
                *(float4*)(smem + SM_B + row * (TPAD*2) + c16 * 16) =
                    *(const float4*)(bw + row * HID + c16 * 8);
            }
        }
        __syncthreads();

        // ---- MMA over this 128-K chunk ----
        #pragma unroll
        for (int k0 = 0; k0 < HID; k0 += 16) {
            uint32_t a[2][4];
            {
                int ar = mW + (lane & 15);
                int ac = k0 + ((lane >> 4) << 3);
                ldsm_x4(a[0], sb + SM_A + (uint32_t)ar * (TPAD*2) + ac * 2);
                ldsm_x4(a[1], sb + SM_A + (uint32_t)(ar + 16) * (TPAD*2) + ac * 2);
            }
            uint32_t b[4][2];
            #pragma unroll
            for (int p = 0; p < 2; p++) {
                int g  = lane >> 3;
                int nn = nW + p * 16 + (lane & 7) + ((g >> 1) << 3);
                int kk = k0 + ((g & 1) << 3);
                uint32_t r[4];
                ldsm_x4(r, sb + SM_B + (uint32_t)nn * (TPAD*2) + kk * 2);
                b[p*2][0] = r[0]; b[p*2][1] = r[1];
                b[p*2+1][0] = r[2]; b[p*2+1][1] = r[3];
            }
            #pragma unroll
            for (int mt = 0; mt < 2; mt++)
                #pragma unroll
                for (int nt = 0; nt < 4; nt++)
                    mma_f16(acc[mt][nt], a[mt], b[nt]);
        }
    }

    // ---- epilogue: + bias (+ relu), store fp32 (final) or fp16 (interm) ----
    #pragma unroll
    for (int mt = 0; mt < 2; mt++) {
        int r0 = rowBase + mW + mt * 16 + (lane >> 2);
        int r1 = r0 + 8;
        #pragma unroll
        for (int nt = 0; nt < 4; nt++) {
            int col = nW + nt * 8 + (lane & 3) * 2;
            float b0 = bias[col], b1 = bias[col + 1];
            float v00 = acc[mt][nt][0] + b0, v01 = acc[mt][nt][1] + b1;
            float v10 = acc[mt][nt][2] + b0, v11 = acc[mt][nt][3] + b1;
            if (reluStore) {
                v00 = fmaxf(v00, 0.f); v01 = fmaxf(v01, 0.f);
                v10 = fmaxf(v10, 0.f); v11 = fmaxf(v11, 0.f);
            }
            if (outf) {
                if (r0 < N_NODES)
                    *(float2*)(outf + (size_t)r0 * HID + col) = make_float2(v00, v01);
                if (r1 < N_NODES)
                    *(float2*)(outf + (size_t)r1 * HID + col) = make_float2(v10, v11);
            } else {
                if (r0 < N_NODES) {
                    __half2 h = __floats2half2_rn(v00, v01);
                    *(uint32_t*)(outh + (size_t)r0 * HID + col) = *(uint32_t*)&h;
                }
                if (r1 < N_NODES) {
                    __half2 h = __floats2half2_rn(v10, v11);
                    *(uint32_t*)(outh + (size_t)r1 * HID + col) = *(uint32_t*)&h;
                }
            }
        }
    }
}

// ================= launch ================================================
extern "C" void kernel_launch(void* const* d_in, const int* in_sizes, int n_in,
                              void* d_out, int out_size)
{
    const int*   edge_index = (const int*)d_in[0];
    const int*   edge_type  = (const int*)d_in[1];
    const float* node_init  = (const float*)d_in[2];
    const float* W          = (const float*)d_in[3];
    const float* root       = (const float*)d_in[4];
    const float* bias       = (const float*)d_in[5];
    float*       out        = (float*)d_out;

    void* p;
    cudaGetSymbolAddress(&p, g_xh0); __half* xh0 = (__half*)p;
    cudaGetSymbolAddress(&p, g_xhA); __half* xhA = (__half*)p;
    cudaGetSymbolAddress(&p, g_xhB); __half* xhB = (__half*)p;
    cudaGetSymbolAddress(&p, g_w);   __half* w   = (__half*)p;

    cudaFuncSetAttribute(rgcn_gemm,
                         cudaFuncAttributeMaxDynamicSharedMemorySize, SM_TOTAL);

    const int scanBlocks = (NSEG + 1023) / 1024;   // 782
    prep0_kernel<<<(X_ELEMS + 255) / 256, 256>>>(W, root, node_init);
    prep_edges_kernel<<<(N_EDGES + 255) / 256, 256>>>(edge_index, edge_type);
    scan1_kernel<<<scanBlocks, 256>>>();
    scan2_kernel<<<1, 256>>>(scanBlocks);
    bin_edges_kernel<<<(N_EDGES + 255) / 256, 256>>>();

    const int rowTiles = (N_NODES + 127) / 128;    // 391
    const __half* xin = xh0;

    for (int l = 0; l < N_LAYERS; l++) {
        int last = (l == N_LAYERS - 1);
        __half* xoutH = last ? nullptr : (l == 0 ? xhA : xhB);
        float*  xoutF = last ? out : nullptr;
        int reluStore = last ? 0 : 1;
        agg_kernel<<<NSEG / 8, 256>>>(xin);
        rgcn_gemm<<<rowTiles, 512, SM_TOTAL>>>(
            xin, w + (size_t)l * NCHUNK * 16384,
            bias + (size_t)l * HID, xoutF, xoutH, reluStore);
        xin = xoutH;
    }
}

// round 14
// speedup vs baseline: 2.6989x; 1.0881x over previous
#include <cuda_runtime.h>
#include <cuda_fp16.h>
#include <cstdint>

#define N_NODES  50000
#define N_REL    16
#define HID      128
#define N_LAYERS 3
#define N_EDGES  1600000
#define NSEG     (N_NODES * N_REL)   // 800000
#define KTOT     (N_REL * HID)       // 2048
#define NCHUNK   (N_REL + 1)         // 16 relations + root
#define W_ELEMS  (N_LAYERS * NCHUNK * 16384)
#define X_ELEMS  (N_NODES * HID)     // 6.4M

// ================= device scratch (no cudaMalloc allowed) =================
__device__ __align__(16) __half g_agg[(size_t)N_NODES * KTOT];   // 204.8 MB fp16
__device__ __align__(16) __half g_xh0[(size_t)X_ELEMS];  // fp16 node_init
__device__ __align__(16) __half g_xhA[(size_t)X_ELEMS];  // fp16 layer outputs
__device__ __align__(16) __half g_xhB[(size_t)X_ELEMS];
// weight stack: per layer 17 tiles of [n][k] fp16 (16 relations + root)
__device__ __align__(16) __half g_w[(size_t)W_ELEMS];
__device__ int g_cnt[NSEG];
__device__ int g_segstart[NSEG];  // block-local scan (finalize with blkoff)
__device__ int g_cursor[NSEG];
__device__ int g_blksum[1024];
__device__ int g_blkoff[1024];
__device__ int g_srcSorted[N_EDGES];

// ================= helpers =================
__device__ __forceinline__ uint32_t smem_to_u32(const void* p) {
    uint32_t a;
    asm("{ .reg .u64 t; cvta.to.shared.u64 t, %1; cvt.u32.u64 %0, t; }"
        : "=r"(a) : "l"(p));
    return a;
}
__device__ __forceinline__ void ldsm_x4(uint32_t* r, uint32_t addr) {
    asm volatile("ldmatrix.sync.aligned.m8n8.x4.shared.b16 {%0,%1,%2,%3}, [%4];"
        : "=r"(r[0]), "=r"(r[1]), "=r"(r[2]), "=r"(r[3]) : "r"(addr));
}
__device__ __forceinline__ void mma_f16(float* d, const uint32_t* a, const uint32_t* b) {
    asm volatile("mma.sync.aligned.m16n8k16.row.col.f32.f16.f16.f32 "
        "{%0,%1,%2,%3}, {%4,%5,%6,%7}, {%8,%9}, {%0,%1,%2,%3};"
        : "+f"(d[0]), "+f"(d[1]), "+f"(d[2]), "+f"(d[3])
        : "r"(a[0]), "r"(a[1]), "r"(a[2]), "r"(a[3]), "r"(b[0]), "r"(b[1]));
}

// ================= prep (5 launches) =======================================
// k1: zero counters + convert weights + convert node_init to fp16
__global__ void prep0_kernel(const float* __restrict__ W,
                             const float* __restrict__ root,
                             const float* __restrict__ x0) {
    int t = blockIdx.x * blockDim.x + threadIdx.x;
    if (t < NSEG) { g_cnt[t] = 0; g_cursor[t] = 0; }
    if (t < W_ELEMS) {
        int tt  = t >> 14;
        int rem = t & 16383;
        int n = rem >> 7;
        int k = rem & 127;
        int l = tt / NCHUNK;
        int c = tt % NCHUNK;
        float v;
        if (c < N_REL) v = W[(((size_t)l * N_REL + c) * HID + k) * HID + n];
        else           v = root[((size_t)l * HID + k) * HID + n];
        g_w[(size_t)tt * 16384 + n * HID + k] = __float2half_rn(v);
    }
    if (t < X_ELEMS) g_xh0[t] = __float2half_rn(x0[t]);
}
// k2: histogram only (edges re-read in bin)
__global__ void prep_edges_kernel(const int* __restrict__ edge_index,
                                  const int* __restrict__ edge_type) {
    int e = blockIdx.x * blockDim.x + threadIdx.x;
    if (e >= N_EDGES) return;
    int s = edge_index[e];
    int t = edge_index[N_EDGES + e];
    int r = edge_type[e];
    if ((unsigned)s >= N_NODES || (unsigned)t >= N_NODES || (unsigned)r >= N_REL)
        return;
    atomicAdd(&g_cnt[t * N_REL + r], 1);
}
__global__ void scan1_kernel() {
    __shared__ int s[256];
    int base = blockIdx.x * 1024;
    int t = threadIdx.x;
    int v[4]; int sum = 0;
    #pragma unroll
    for (int j = 0; j < 4; j++) {
        int idx = base + t * 4 + j;
        v[j] = (idx < NSEG) ? g_cnt[idx] : 0;
        sum += v[j];
    }
    s[t] = sum; __syncthreads();
    for (int off = 1; off < 256; off <<= 1) {
        int x = 0;
        if (t >= off) x = s[t - off];
        __syncthreads();
        if (t >= off) s[t] += x;
        __syncthreads();
    }
    int excl = (t > 0) ? s[t - 1] : 0;
    if (t == 255) g_blksum[blockIdx.x] = s[255];
    int run = excl;
    #pragma unroll
    for (int j = 0; j < 4; j++) {
        int idx = base + t * 4 + j;
        if (idx < NSEG) g_segstart[idx] = run;
        run += v[j];
    }
}
__global__ void scan2_kernel(int nb) {
    __shared__ int s[256];
    int t = threadIdx.x;
    int v[4]; int sum = 0;
    #pragma unroll
    for (int j = 0; j < 4; j++) {
        int idx = t * 4 + j;
        v[j] = (idx < nb) ? g_blksum[idx] : 0;
        sum += v[j];
    }
    s[t] = sum; __syncthreads();
    for (int off = 1; off < 256; off <<= 1) {
        int x = 0;
        if (t >= off) x = s[t - off];
        __syncthreads();
        if (t >= off) s[t] += x;
        __syncthreads();
    }
    int excl = (t > 0) ? s[t - 1] : 0;
    int run = excl;
    #pragma unroll
    for (int j = 0; j < 4; j++) {
        int idx = t * 4 + j;
        if (idx < nb) g_blkoff[idx] = run;
        run += v[j];
    }
}
// k5: counting-sort bin (recomputes seg/src from raw edges)
__global__ void bin_edges_kernel(const int* __restrict__ edge_index,
                                 const int* __restrict__ edge_type) {
    int e = blockIdx.x * blockDim.x + threadIdx.x;
    if (e >= N_EDGES) return;
    int s = edge_index[e];
    int t = edge_index[N_EDGES + e];
    int r = edge_type[e];
    if ((unsigned)s >= N_NODES || (unsigned)t >= N_NODES || (unsigned)r >= N_REL)
        return;
    int seg = t * N_REL + r;
    int base = g_segstart[seg] + g_blkoff[seg >> 10];
    int pos = base + atomicAdd(&g_cursor[seg], 1);
    g_srcSorted[pos] = s;
}

// ================= full-range aggregation (no atomics) =====================
// TWO segments per warp: 16 lanes each, lane loads uint4 (8 halfs = 16B).
// Edge loop 2-way unrolled for MLP. fp32 accumulate, fp16 mean out (.cs).
__global__ __launch_bounds__(256) void agg_kernel(const __half* __restrict__ xh)
{
    int seg = (blockIdx.x * 256 + threadIdx.x) >> 4;   // one segment per 16 lanes
    int lane = threadIdx.x & 15;
    if (seg >= NSEG) return;
    int st = g_segstart[seg] + g_blkoff[seg >> 10];
    int c  = g_cnt[seg];

    float s0 = 0.f, s1 = 0.f, s2 = 0.f, s3 = 0.f,
          s4 = 0.f, s5 = 0.f, s6 = 0.f, s7 = 0.f;
    int i = 0;
    for (; i + 2 <= c; i += 2) {
        int n0 = __ldg(g_srcSorted + st + i);
        int n1 = __ldg(g_srcSorted + st + i + 1);
        uint4 ra = __ldg((const uint4*)(xh + (size_t)n0 * HID) + lane);
        uint4 rb = __ldg((const uint4*)(xh + (size_t)n1 * HID) + lane);
        float2 f;
        f = __half22float2(*(__half2*)&ra.x); s0 += f.x; s1 += f.y;
        f = __half22float2(*(__half2*)&ra.y); s2 += f.x; s3 += f.y;
        f = __half22float2(*(__half2*)&ra.z); s4 += f.x; s5 += f.y;
        f = __half22float2(*(__half2*)&ra.w); s6 += f.x; s7 += f.y;
        f = __half22float2(*(__half2*)&rb.x); s0 += f.x; s1 += f.y;
        f = __half22float2(*(__half2*)&rb.y); s2 += f.x; s3 += f.y;
        f = __half22float2(*(__half2*)&rb.z); s4 += f.x; s5 += f.y;
        f = __half22float2(*(__half2*)&rb.w); s6 += f.x; s7 += f.y;
    }
    if (i < c) {
        int n0 = __ldg(g_srcSorted + st + i);
        uint4 ra = __ldg((const uint4*)(xh + (size_t)n0 * HID) + lane);
        float2 f;
        f = __half22float2(*(__half2*)&ra.x); s0 += f.x; s1 += f.y;
        f = __half22float2(*(__half2*)&ra.y); s2 += f.x; s3 += f.y;
        f = __half22float2(*(__half2*)&ra.z); s4 += f.x; s5 += f.y;
        f = __half22float2(*(__half2*)&ra.w); s6 += f.x; s7 += f.y;
    }
    float inv = (c > 0) ? 1.0f / (float)c : 0.0f;
    __half2 p0 = __floats2half2_rn(s0 * inv, s1 * inv);
    __half2 p1 = __floats2half2_rn(s2 * inv, s3 * inv);
    __half2 p2 = __floats2half2_rn(s4 * inv, s5 * inv);
    __half2 p3 = __floats2half2_rn(s6 * inv, s7 * inv);
    size_t off = (size_t)seg * HID + lane * 8;   // seg*128 = node*2048 + rel*128
    asm volatile("st.global.cs.v4.b32 [%0], {%1,%2,%3,%4};"
                 :: "l"(g_agg + off),
                    "r"(*(uint32_t*)&p0), "r"(*(uint32_t*)&p1),
                    "r"(*(uint32_t*)&p2), "r"(*(uint32_t*)&p3)
                 : "memory");
}

// ================= layer GEMM: out = [agg | x] @ [Wstk; root] + bias =======
// K = 17 chunks x 128. 512 threads / 16 warps (32x32 warp tiles).
// Single fp16 MMA term; 2 CTAs/SM (68KB smem). Intermediate layers store
// fp16 (outh); final layer stores fp32 (outf).
#define TPAD      136
#define TILE_B    (128 * TPAD * 2)           // 34816 bytes
#define SM_A      0
#define SM_B      (SM_A + TILE_B)
#define SM_TOTAL  (SM_B + TILE_B)            // 69632

__global__ __launch_bounds__(512, 2) void rgcn_gemm(
    const __half* __restrict__ xh,           // fp16 activations (pre-activated)
    const __half* __restrict__ w,            // layer's 17-tile stack
    const float* __restrict__ bias,
    float* __restrict__ outf,                // final-layer fp32 out (or null)
    __half* __restrict__ outh,               // intermediate fp16 out (or null)
    int reluStore)
{
    extern __shared__ __align__(16) char smem[];
    const uint32_t sb = smem_to_u32(smem);
    const int tid  = threadIdx.x;
    const int wid  = tid >> 5;
    const int lane = tid & 31;
    const int rowBase = blockIdx.x * 128;

    const int mW = (wid & 3) * 32;
    const int nW = (wid >> 2) * 32;

    float acc[2][4][4];
    #pragma unroll
    for (int mt = 0; mt < 2; mt++)
        #pragma unroll
        for (int nt = 0; nt < 4; nt++)
            #pragma unroll
            for (int q = 0; q < 4; q++) acc[mt][nt][q] = 0.0f;

    for (int kc = 0; kc < NCHUNK; kc++) {
        __syncthreads();   // prior chunk's ldsm reads complete
        // ---- A chunk: fp16 rows (agg for kc<16, x for root chunk) ----
        {
            const __half* asrc;
            size_t rowStride;
            if (kc < N_REL) { asrc = g_agg + (size_t)kc * HID; rowStride = KTOT; }
            else            { asrc = xh;                        rowStride = HID;  }
            #pragma unroll
            for (int i = 0; i < 4; i++) {
                int idx4 = tid + i * 512;        // 0..2047
                int row = idx4 >> 4, c16 = idx4 & 15;
                int gr = rowBase + row;
                float4 v = make_float4(0.f,0.f,0.f,0.f);
                if (gr < N_NODES)
                    v = __ldg((const float4*)(asrc + (size_t)gr * rowStride) + c16);
                *(float4*)(smem + SM_A + row * (TPAD*2) + c16 * 16) = v;
            }
        }
        // ---- B chunk (L2-resident weight stack) ----
        {
            const __half* bw = w + (size_t)kc * 16384;
            #pragma unroll
            for (int i = 0; i < 4; i++) {
                int idx4 = tid + i * 512;        // 0..2047
                int row = idx4 >> 4, c16 = idx4 & 15;
                *(float4*)(smem + SM_B + row * (TPAD*2) + c16 * 16) =
                    *(const float4*)(bw + row * HID + c16 * 8);
            }
        }
        __syncthreads();

        // ---- MMA over this 128-K chunk ----
        #pragma unroll
        for (int k0 = 0; k0 < HID; k0 += 16) {
            uint32_t a[2][4];
            {
                int ar = mW + (lane & 15);
                int ac = k0 + ((lane >> 4) << 3);
                ldsm_x4(a[0], sb + SM_A + (uint32_t)ar * (TPAD*2) + ac * 2);
                ldsm_x4(a[1], sb + SM_A + (uint32_t)(ar + 16) * (TPAD*2) + ac * 2);
            }
            uint32_t b[4][2];
            #pragma unroll
            for (int p = 0; p < 2; p++) {
                int g  = lane >> 3;
                int nn = nW + p * 16 + (lane & 7) + ((g >> 1) << 3);
                int kk = k0 + ((g & 1) << 3);
                uint32_t r[4];
                ldsm_x4(r, sb + SM_B + (uint32_t)nn * (TPAD*2) + kk * 2);
                b[p*2][0] = r[0]; b[p*2][1] = r[1];
                b[p*2+1][0] = r[2]; b[p*2+1][1] = r[3];
            }
            #pragma unroll
            for (int mt = 0; mt < 2; mt++)
                #pragma unroll
                for (int nt = 0; nt < 4; nt++)
                    mma_f16(acc[mt][nt], a[mt], b[nt]);
        }
    }

    // ---- epilogue: + bias (+ relu), store fp32 (final) or fp16 (interm) ----
    #pragma unroll
    for (int mt = 0; mt < 2; mt++) {
        int r0 = rowBase + mW + mt * 16 + (lane >> 2);
        int r1 = r0 + 8;
        #pragma unroll
        for (int nt = 0; nt < 4; nt++) {
            int col = nW + nt * 8 + (lane & 3) * 2;
            float b0 = bias[col], b1 = bias[col + 1];
            float v00 = acc[mt][nt][0] + b0, v01 = acc[mt][nt][1] + b1;
            float v10 = acc[mt][nt][2] + b0, v11 = acc[mt][nt][3] + b1;
            if (reluStore) {
                v00 = fmaxf(v00, 0.f); v01 = fmaxf(v01, 0.f);
                v10 = fmaxf(v10, 0.f); v11 = fmaxf(v11, 0.f);
            }
            if (outf) {
                if (r0 < N_NODES)
                    *(float2*)(outf + (size_t)r0 * HID + col) = make_float2(v00, v01);
                if (r1 < N_NODES)
                    *(float2*)(outf + (size_t)r1 * HID + col) = make_float2(v10, v11);
            } else {
                if (r0 < N_NODES) {
                    __half2 h = __floats2half2_rn(v00, v01);
                    *(uint32_t*)(outh + (size_t)r0 * HID + col) = *(uint32_t*)&h;
                }
                if (r1 < N_NODES) {
                    __half2 h = __floats2half2_rn(v10, v11);
                    *(uint32_t*)(outh + (size_t)r1 * HID + col) = *(uint32_t*)&h;
                }
            }
        }
    }
}

// ================= launch ================================================
extern "C" void kernel_launch(void* const* d_in, const int* in_sizes, int n_in,
                              void* d_out, int out_size)
{
    const int*   edge_index = (const int*)d_in[0];
    const int*   edge_type  = (const int*)d_in[1];
    const float* node_init  = (const float*)d_in[2];
    const float* W          = (const float*)d_in[3];
    const float* root       = (const float*)d_in[4];
    const float* bias       = (const float*)d_in[5];
    float*       out        = (float*)d_out;

    void* p;
    cudaGetSymbolAddress(&p, g_xh0); __half* xh0 = (__half*)p;
    cudaGetSymbolAddress(&p, g_xhA); __half* xhA = (__half*)p;
    cudaGetSymbolAddress(&p, g_xhB); __half* xhB = (__half*)p;
    cudaGetSymbolAddress(&p, g_w);   __half* w   = (__half*)p;

    cudaFuncSetAttribute(rgcn_gemm,
                         cudaFuncAttributeMaxDynamicSharedMemorySize, SM_TOTAL);

    const int scanBlocks = (NSEG + 1023) / 1024;   // 782
    prep0_kernel<<<(X_ELEMS + 255) / 256, 256>>>(W, root, node_init);
    prep_edges_kernel<<<(N_EDGES + 255) / 256, 256>>>(edge_index, edge_type);
    scan1_kernel<<<scanBlocks, 256>>>();
    scan2_kernel<<<1, 256>>>(scanBlocks);
    bin_edges_kernel<<<(N_EDGES + 255) / 256, 256>>>(edge_index, edge_type);

    const int rowTiles = (N_NODES + 127) / 128;    // 391
    const __half* xin = xh0;

    for (int l = 0; l < N_LAYERS; l++) {
        int last = (l == N_LAYERS - 1);
        __half* xoutH = last ? nullptr : (l == 0 ? xhA : xhB);
        float*  xoutF = last ? out : nullptr;
        int reluStore = last ? 0 : 1;
        agg_kernel<<<NSEG / 16, 256>>>(xin);
        rgcn_gemm<<<rowTiles, 512, SM_TOTAL>>>(
            xin, w + (size_t)l * NCHUNK * 16384,
            bias + (size_t)l * HID, xoutF, xoutH, reluStore);
        xin = xoutH;
    }
}

// round 15
// speedup vs baseline: 3.3049x; 1.2245x over previous
#include <cuda_runtime.h>
#include <cuda_fp16.h>
#include <cstdint>

#define N_NODES  50000
#define N_REL    16
#define HID      128
#define N_LAYERS 3
#define N_EDGES  1600000
#define NSEG     (N_NODES * N_REL)   // 800000
#define KTOT     (N_REL * HID)       // 2048
#define NCHUNK   (N_REL + 1)         // 16 relations + root
#define W_ELEMS  (N_LAYERS * NCHUNK * 16384)
#define X_ELEMS  (N_NODES * HID)     // 6.4M

// ================= device scratch (no cudaMalloc allowed) =================
__device__ __align__(16) __half g_agg[(size_t)N_NODES * KTOT];   // 204.8 MB fp16
__device__ __align__(16) __half g_xh0[(size_t)X_ELEMS];  // fp16 node_init
__device__ __align__(16) __half g_xhA[(size_t)X_ELEMS];  // fp16 layer outputs
__device__ __align__(16) __half g_xhB[(size_t)X_ELEMS];
// weight stack: per layer 17 tiles of [n][k] fp16 (16 relations + root)
__device__ __align__(16) __half g_w[(size_t)W_ELEMS];
__device__ int g_cnt[NSEG];
__device__ int g_segstart[NSEG];  // block-local scan (finalize with blkoff)
__device__ int g_cursor[NSEG];
__device__ int g_blksum[1024];
__device__ int g_blkoff[1024];
__device__ int g_srcSorted[N_EDGES];

// ================= helpers =================
__device__ __forceinline__ uint32_t smem_to_u32(const void* p) {
    uint32_t a;
    asm("{ .reg .u64 t; cvta.to.shared.u64 t, %1; cvt.u32.u64 %0, t; }"
        : "=r"(a) : "l"(p));
    return a;
}
__device__ __forceinline__ void ldsm_x4(uint32_t* r, uint32_t addr) {
    asm volatile("ldmatrix.sync.aligned.m8n8.x4.shared.b16 {%0,%1,%2,%3}, [%4];"
        : "=r"(r[0]), "=r"(r[1]), "=r"(r[2]), "=r"(r[3]) : "r"(addr));
}
__device__ __forceinline__ void mma_f16(float* d, const uint32_t* a, const uint32_t* b) {
    asm volatile("mma.sync.aligned.m16n8k16.row.col.f32.f16.f16.f32 "
        "{%0,%1,%2,%3}, {%4,%5,%6,%7}, {%8,%9}, {%0,%1,%2,%3};"
        : "+f"(d[0]), "+f"(d[1]), "+f"(d[2]), "+f"(d[3])
        : "r"(a[0]), "r"(a[1]), "r"(a[2]), "r"(a[3]), "r"(b[0]), "r"(b[1]));
}
#define CP_ASYNC_16(dst, src, sz) \
    asm volatile("cp.async.cg.shared.global [%0], [%1], 16, %2;" \
                 :: "r"(dst), "l"(src), "r"(sz))
#define CP_ASYNC_COMMIT() asm volatile("cp.async.commit_group;" ::: "memory")
#define CP_ASYNC_WAIT0()  asm volatile("cp.async.wait_group 0;" ::: "memory")

// ================= prep (5 launches) =======================================
// k1: zero counters + convert weights + convert node_init to fp16
__global__ void prep0_kernel(const float* __restrict__ W,
                             const float* __restrict__ root,
                             const float* __restrict__ x0) {
    int t = blockIdx.x * blockDim.x + threadIdx.x;
    if (t < NSEG) { g_cnt[t] = 0; g_cursor[t] = 0; }
    if (t < W_ELEMS) {
        int tt  = t >> 14;
        int rem = t & 16383;
        int n = rem >> 7;
        int k = rem & 127;
        int l = tt / NCHUNK;
        int c = tt % NCHUNK;
        float v;
        if (c < N_REL) v = W[(((size_t)l * N_REL + c) * HID + k) * HID + n];
        else           v = root[((size_t)l * HID + k) * HID + n];
        g_w[(size_t)tt * 16384 + n * HID + k] = __float2half_rn(v);
    }
    if (t < X_ELEMS) g_xh0[t] = __float2half_rn(x0[t]);
}
// k2: histogram only (edges re-read in bin)
__global__ void prep_edges_kernel(const int* __restrict__ edge_index,
                                  const int* __restrict__ edge_type) {
    int e = blockIdx.x * blockDim.x + threadIdx.x;
    if (e >= N_EDGES) return;
    int s = edge_index[e];
    int t = edge_index[N_EDGES + e];
    int r = edge_type[e];
    if ((unsigned)s >= N_NODES || (unsigned)t >= N_NODES || (unsigned)r >= N_REL)
        return;
    atomicAdd(&g_cnt[t * N_REL + r], 1);
}
__global__ void scan1_kernel() {
    __shared__ int s[256];
    int base = blockIdx.x * 1024;
    int t = threadIdx.x;
    int v[4]; int sum = 0;
    #pragma unroll
    for (int j = 0; j < 4; j++) {
        int idx = base + t * 4 + j;
        v[j] = (idx < NSEG) ? g_cnt[idx] : 0;
        sum += v[j];
    }
    s[t] = sum; __syncthreads();
    for (int off = 1; off < 256; off <<= 1) {
        int x = 0;
        if (t >= off) x = s[t - off];
        __syncthreads();
        if (t >= off) s[t] += x;
        __syncthreads();
    }
    int excl = (t > 0) ? s[t - 1] : 0;
    if (t == 255) g_blksum[blockIdx.x] = s[255];
    int run = excl;
    #pragma unroll
    for (int j = 0; j < 4; j++) {
        int idx = base + t * 4 + j;
        if (idx < NSEG) g_segstart[idx] = run;
        run += v[j];
    }
}
__global__ void scan2_kernel(int nb) {
    __shared__ int s[256];
    int t = threadIdx.x;
    int v[4]; int sum = 0;
    #pragma unroll
    for (int j = 0; j < 4; j++) {
        int idx = t * 4 + j;
        v[j] = (idx < nb) ? g_blksum[idx] : 0;
        sum += v[j];
    }
    s[t] = sum; __syncthreads();
    for (int off = 1; off < 256; off <<= 1) {
        int x = 0;
        if (t >= off) x = s[t - off];
        __syncthreads();
        if (t >= off) s[t] += x;
        __syncthreads();
    }
    int excl = (t > 0) ? s[t - 1] : 0;
    int run = excl;
    #pragma unroll
    for (int j = 0; j < 4; j++) {
        int idx = t * 4 + j;
        if (idx < nb) g_blkoff[idx] = run;
        run += v[j];
    }
}
// k5: counting-sort bin (recomputes seg/src from raw edges)
__global__ void bin_edges_kernel(const int* __restrict__ edge_index,
                                 const int* __restrict__ edge_type) {
    int e = blockIdx.x * blockDim.x + threadIdx.x;
    if (e >= N_EDGES) return;
    int s = edge_index[e];
    int t = edge_index[N_EDGES + e];
    int r = edge_type[e];
    if ((unsigned)s >= N_NODES || (unsigned)t >= N_NODES || (unsigned)r >= N_REL)
        return;
    int seg = t * N_REL + r;
    int base = g_segstart[seg] + g_blkoff[seg >> 10];
    int pos = base + atomicAdd(&g_cursor[seg], 1);
    g_srcSorted[pos] = s;
}

// ================= full-range aggregation (no atomics) =====================
// TWO segments per warp: 16 lanes each, lane loads uint4 (8 halfs = 16B).
// Edge loop 2-way unrolled for MLP. fp32 accumulate, fp16 mean out (.cs).
__global__ __launch_bounds__(256) void agg_kernel(const __half* __restrict__ xh)
{
    int seg = (blockIdx.x * 256 + threadIdx.x) >> 4;   // one segment per 16 lanes
    int lane = threadIdx.x & 15;
    if (seg >= NSEG) return;
    int st = g_segstart[seg] + g_blkoff[seg >> 10];
    int c  = g_cnt[seg];

    float s0 = 0.f, s1 = 0.f, s2 = 0.f, s3 = 0.f,
          s4 = 0.f, s5 = 0.f, s6 = 0.f, s7 = 0.f;
    int i = 0;
    for (; i + 2 <= c; i += 2) {
        int n0 = __ldg(g_srcSorted + st + i);
        int n1 = __ldg(g_srcSorted + st + i + 1);
        uint4 ra = __ldg((const uint4*)(xh + (size_t)n0 * HID) + lane);
        uint4 rb = __ldg((const uint4*)(xh + (size_t)n1 * HID) + lane);
        float2 f;
        f = __half22float2(*(__half2*)&ra.x); s0 += f.x; s1 += f.y;
        f = __half22float2(*(__half2*)&ra.y); s2 += f.x; s3 += f.y;
        f = __half22float2(*(__half2*)&ra.z); s4 += f.x; s5 += f.y;
        f = __half22float2(*(__half2*)&ra.w); s6 += f.x; s7 += f.y;
        f = __half22float2(*(__half2*)&rb.x); s0 += f.x; s1 += f.y;
        f = __half22float2(*(__half2*)&rb.y); s2 += f.x; s3 += f.y;
        f = __half22float2(*(__half2*)&rb.z); s4 += f.x; s5 += f.y;
        f = __half22float2(*(__half2*)&rb.w); s6 += f.x; s7 += f.y;
    }
    if (i < c) {
        int n0 = __ldg(g_srcSorted + st + i);
        uint4 ra = __ldg((const uint4*)(xh + (size_t)n0 * HID) + lane);
        float2 f;
        f = __half22float2(*(__half2*)&ra.x); s0 += f.x; s1 += f.y;
        f = __half22float2(*(__half2*)&ra.y); s2 += f.x; s3 += f.y;
        f = __half22float2(*(__half2*)&ra.z); s4 += f.x; s5 += f.y;
        f = __half22float2(*(__half2*)&ra.w); s6 += f.x; s7 += f.y;
    }
    float inv = (c > 0) ? 1.0f / (float)c : 0.0f;
    __half2 p0 = __floats2half2_rn(s0 * inv, s1 * inv);
    __half2 p1 = __floats2half2_rn(s2 * inv, s3 * inv);
    __half2 p2 = __floats2half2_rn(s4 * inv, s5 * inv);
    __half2 p3 = __floats2half2_rn(s6 * inv, s7 * inv);
    size_t off = (size_t)seg * HID + lane * 8;   // seg*128 = node*2048 + rel*128
    asm volatile("st.global.cs.v4.b32 [%0], {%1,%2,%3,%4};"
                 :: "l"(g_agg + off),
                    "r"(*(uint32_t*)&p0), "r"(*(uint32_t*)&p1),
                    "r"(*(uint32_t*)&p2), "r"(*(uint32_t*)&p3)
                 : "memory");
}

// ================= layer GEMM: out = [agg | x] @ [Wstk; root] + bias =======
// K = 17 chunks x 128. 512 threads / 16 warps (32x32 warp tiles).
// cp.async pipeline: A (agg, DRAM) double-buffered & prefetched behind MMA;
// B (weights, L2-hit) single-buffered. 102KB smem -> 2 CTAs/SM.
#define TPAD      136
#define TILE_B    (128 * TPAD * 2)           // 34816 bytes
#define SM_A0     0
#define SM_A1     (SM_A0 + TILE_B)
#define SM_B      (SM_A1 + TILE_B)
#define SM_TOTAL  (SM_B + TILE_B)            // 104448

__global__ __launch_bounds__(512, 2) void rgcn_gemm(
    const __half* __restrict__ xh,           // fp16 activations (pre-activated)
    const __half* __restrict__ w,            // layer's 17-tile stack
    const float* __restrict__ bias,
    float* __restrict__ outf,                // final-layer fp32 out (or null)
    __half* __restrict__ outh,               // intermediate fp16 out (or null)
    int reluStore)
{
    extern __shared__ __align__(16) char smem[];
    const uint32_t sb = smem_to_u32(smem);
    const int tid  = threadIdx.x;
    const int wid  = tid >> 5;
    const int lane = tid & 31;
    const int rowBase = blockIdx.x * 128;

    const int mW = (wid & 3) * 32;
    const int nW = (wid >> 2) * 32;

    // per-thread fixed copy coordinates (4 fragments of 16B each)
    // idx4 = tid + i*512 ; row = idx4>>4 ; c16 = idx4&15
    // A src for chunk kc<16: g_agg + gr*KTOT + kc*HID + c16*8
    //          chunk 16    : xh + gr*HID + c16*8

    auto issueA = [&](int kc, uint32_t buf) {
        #pragma unroll
        for (int i = 0; i < 4; i++) {
            int idx4 = tid + i * 512;
            int row = idx4 >> 4, c16 = idx4 & 15;
            int gr = rowBase + row;
            const __half* src;
            if (kc < N_REL) src = g_agg + (size_t)gr * KTOT + (size_t)kc * HID + c16 * 8;
            else            src = xh + (size_t)gr * HID + c16 * 8;
            uint32_t sz = 16;
            if (gr >= N_NODES) { src = xh; sz = 0; }   // zero-fill OOB rows
            uint32_t dst = sb + buf + (uint32_t)row * (TPAD*2) + c16 * 16;
            CP_ASYNC_16(dst, src, sz);
        }
    };
    auto issueB = [&](int kc) {
        const __half* bw = w + (size_t)kc * 16384;
        #pragma unroll
        for (int i = 0; i < 4; i++) {
            int idx4 = tid + i * 512;
            int row = idx4 >> 4, c16 = idx4 & 15;
            uint32_t dst = sb + SM_B + (uint32_t)row * (TPAD*2) + c16 * 16;
            CP_ASYNC_16(dst, bw + row * HID + c16 * 8, 16);
        }
    };

    float acc[2][4][4];
    #pragma unroll
    for (int mt = 0; mt < 2; mt++)
        #pragma unroll
        for (int nt = 0; nt < 4; nt++)
            #pragma unroll
            for (int q = 0; q < 4; q++) acc[mt][nt][q] = 0.0f;

    // prologue: chunk 0 into A0 + B
    issueA(0, SM_A0);
    issueB(0);
    CP_ASYNC_COMMIT();
    CP_ASYNC_WAIT0();
    __syncthreads();

    for (int kc = 0; kc < NCHUNK; kc++) {
        const uint32_t aBase = sb + ((kc & 1) ? SM_A1 : SM_A0);

        // prefetch next A chunk into the alternate buffer (hidden behind MMA)
        if (kc + 1 < NCHUNK) {
            issueA(kc + 1, (kc & 1) ? SM_A0 : SM_A1);
            CP_ASYNC_COMMIT();
        }

        // ---- MMA over this 128-K chunk ----
        #pragma unroll
        for (int k0 = 0; k0 < HID; k0 += 16) {
            uint32_t a[2][4];
            {
                int ar = mW + (lane & 15);
                int ac = k0 + ((lane >> 4) << 3);
                ldsm_x4(a[0], aBase + (uint32_t)ar * (TPAD*2) + ac * 2);
                ldsm_x4(a[1], aBase + (uint32_t)(ar + 16) * (TPAD*2) + ac * 2);
            }
            uint32_t b[4][2];
            #pragma unroll
            for (int p = 0; p < 2; p++) {
                int g  = lane >> 3;
                int nn = nW + p * 16 + (lane & 7) + ((g >> 1) << 3);
                int kk = k0 + ((g & 1) << 3);
                uint32_t r[4];
                ldsm_x4(r, sb + SM_B + (uint32_t)nn * (TPAD*2) + kk * 2);
                b[p*2][0] = r[0]; b[p*2][1] = r[1];
                b[p*2+1][0] = r[2]; b[p*2+1][1] = r[3];
            }
            #pragma unroll
            for (int mt = 0; mt < 2; mt++)
                #pragma unroll
                for (int nt = 0; nt < 4; nt++)
                    mma_f16(acc[mt][nt], a[mt], b[nt]);
        }

        __syncthreads();   // all warps done reading B (and prev A)
        if (kc + 1 < NCHUNK) {
            issueB(kc + 1);
            CP_ASYNC_COMMIT();
            CP_ASYNC_WAIT0();   // waits B(kc+1) AND prefetched A(kc+1)
            __syncthreads();
        }
    }

    // ---- epilogue: + bias (+ relu), store fp32 (final) or fp16 (interm) ----
    #pragma unroll
    for (int mt = 0; mt < 2; mt++) {
        int r0 = rowBase + mW + mt * 16 + (lane >> 2);
        int r1 = r0 + 8;
        #pragma unroll
        for (int nt = 0; nt < 4; nt++) {
            int col = nW + nt * 8 + (lane & 3) * 2;
            float b0 = bias[col], b1 = bias[col + 1];
            float v00 = acc[mt][nt][0] + b0, v01 = acc[mt][nt][1] + b1;
            float v10 = acc[mt][nt][2] + b0, v11 = acc[mt][nt][3] + b1;
            if (reluStore) {
                v00 = fmaxf(v00, 0.f); v01 = fmaxf(v01, 0.f);
                v10 = fmaxf(v10, 0.f); v11 = fmaxf(v11, 0.f);
            }
            if (outf) {
                if (r0 < N_NODES)
                    *(float2*)(outf + (size_t)r0 * HID + col) = make_float2(v00, v01);
                if (r1 < N_NODES)
                    *(float2*)(outf + (size_t)r1 * HID + col) = make_float2(v10, v11);
            } else {
                if (r0 < N_NODES) {
                    __half2 h = __floats2half2_rn(v00, v01);
                    *(uint32_t*)(outh + (size_t)r0 * HID + col) = *(uint32_t*)&h;
                }
                if (r1 < N_NODES) {
                    __half2 h = __floats2half2_rn(v10, v11);
                    *(uint32_t*)(outh + (size_t)r1 * HID + col) = *(uint32_t*)&h;
                }
            }
        }
    }
}

// ================= launch ================================================
extern "C" void kernel_launch(void* const* d_in, const int* in_sizes, int n_in,
                              void* d_out, int out_size)
{
    const int*   edge_index = (const int*)d_in[0];
    const int*   edge_type  = (const int*)d_in[1];
    const float* node_init  = (const float*)d_in[2];
    const float* W          = (const float*)d_in[3];
    const float* root       = (const float*)d_in[4];
    const float* bias       = (const float*)d_in[5];
    float*       out        = (float*)d_out;

    void* p;
    cudaGetSymbolAddress(&p, g_xh0); __half* xh0 = (__half*)p;
    cudaGetSymbolAddress(&p, g_xhA); __half* xhA = (__half*)p;
    cudaGetSymbolAddress(&p, g_xhB); __half* xhB = (__half*)p;
    cudaGetSymbolAddress(&p, g_w);   __half* w   = (__half*)p;

    cudaFuncSetAttribute(rgcn_gemm,
                         cudaFuncAttributeMaxDynamicSharedMemorySize, SM_TOTAL);

    const int scanBlocks = (NSEG + 1023) / 1024;   // 782
    prep0_kernel<<<(X_ELEMS + 255) / 256, 256>>>(W, root, node_init);
    prep_edges_kernel<<<(N_EDGES + 255) / 256, 256>>>(edge_index, edge_type);
    scan1_kernel<<<scanBlocks, 256>>>();
    scan2_kernel<<<1, 256>>>(scanBlocks);
    bin_edges_kernel<<<(N_EDGES + 255) / 256, 256>>>(edge_index, edge_type);

    const int rowTiles = (N_NODES + 127) / 128;    // 391
    const __half* xin = xh0;

    for (int l = 0; l < N_LAYERS; l++) {
        int last = (l == N_LAYERS - 1);
        __half* xoutH = last ? nullptr : (l == 0 ? xhA : xhB);
        float*  xoutF = last ? out : nullptr;
        int reluStore = last ? 0 : 1;
        agg_kernel<<<NSEG / 16, 256>>>(xin);
        rgcn_gemm<<<rowTiles, 512, SM_TOTAL>>>(
            xin, w + (size_t)l * NCHUNK * 16384,
            bias + (size_t)l * HID, xoutF, xoutH, reluStore);
        xin = xoutH;
    }
}